// round 3
// baseline (speedup 1.0000x reference)
#include <cuda_runtime.h>
#include <cuda_bf16.h>

#define NN 50000
#define EE 600000
#define HID 128
#define NC 21
#define SCAN_T 512
#define NB ((NN + SCAN_T - 1) / SCAN_T)   // 98

// ---------------- scratch (__device__ globals; no cudaMalloc allowed) ------
__device__ __align__(16) float g_h[NN * HID];     // linear-transform output
__device__ __align__(16) float g_agg[NN * HID];   // conv output (post bias+relu)
__device__ float g_dinv[NN];
__device__ int   g_cnt[NN];      // in-degree (without self loop)
__device__ int   g_cur[NN];      // binning cursor
__device__ int   g_rowinc[NN];   // inclusive block-scan
__device__ int   g_row[NN];      // CSR row start (exclusive scan)
__device__ int   g_bsum[NB];     // per-block scan totals
__device__ int   g_csr[EE];      // src node per CSR slot

// ---------------- init: zero counters ----------------
__global__ void k_init() {
    int i = blockIdx.x * blockDim.x + threadIdx.x;
    if (i < NN) { g_cnt[i] = 0; g_cur[i] = 0; }
}

// ---------------- degree count (scalar int atomics) ----------------
// edge_index is int32 on device (JAX x64 disabled downcasts int64 -> int32)
__global__ void k_deg_count(const int* __restrict__ ei) {
    int e = blockIdx.x * blockDim.x + threadIdx.x;
    if (e < EE) atomicAdd(&g_cnt[ei[EE + e]], 1);
}

__global__ void k_dinv() {
    int i = blockIdx.x * blockDim.x + threadIdx.x;
    if (i < NN) g_dinv[i] = rsqrtf((float)(g_cnt[i] + 1));
}

// ---------------- 3-kernel exclusive prefix scan of g_cnt -> g_row ---------
__global__ void k_scan1() {
    __shared__ int sh[SCAN_T];
    int gid = blockIdx.x * SCAN_T + threadIdx.x;
    int v = (gid < NN) ? g_cnt[gid] : 0;
    sh[threadIdx.x] = v;
    __syncthreads();
#pragma unroll
    for (int off = 1; off < SCAN_T; off <<= 1) {
        int t = (threadIdx.x >= off) ? sh[threadIdx.x - off] : 0;
        __syncthreads();
        sh[threadIdx.x] += t;
        __syncthreads();
    }
    if (gid < NN) g_rowinc[gid] = sh[threadIdx.x];
    if (threadIdx.x == SCAN_T - 1) g_bsum[blockIdx.x] = sh[threadIdx.x];
}

__global__ void k_scan2() {
    if (blockIdx.x == 0 && threadIdx.x == 0) {
        int acc = 0;
        for (int i = 0; i < NB; i++) { int t = g_bsum[i]; g_bsum[i] = acc; acc += t; }
    }
}

__global__ void k_scan3() {
    int gid = blockIdx.x * blockDim.x + threadIdx.x;
    if (gid < NN)
        g_row[gid] = g_rowinc[gid] - g_cnt[gid] + g_bsum[gid / SCAN_T];
}

// ---------------- bin edges into CSR slots ----------------
__global__ void k_bin(const int* __restrict__ ei) {
    int e = blockIdx.x * blockDim.x + threadIdx.x;
    if (e >= EE) return;
    int s = ei[e];
    int d = ei[EE + e];
    int pos = g_row[d] + atomicAdd(&g_cur[d], 1);
    g_csr[pos] = s;
}

// ---------------- GEMM: g_h[N,128] = A[N,128] @ W[128,128] -----------------
// warp handles 4 rows; lane owns cols 4*lane..4*lane+3; A==nullptr -> g_agg
__global__ void k_gemm128(const float* __restrict__ A, const float* __restrict__ W) {
    const float* Ap = A ? A : g_agg;
    const int lane = threadIdx.x & 31;
    const int warp = threadIdx.x >> 5;
    const int R = 4;
    int rowBase = (blockIdx.x * (blockDim.x >> 5) + warp) * R;
    if (rowBase >= NN) return;

    float4 xv[R];
#pragma unroll
    for (int r = 0; r < R; r++) {
        int row = rowBase + r;
        xv[r] = (row < NN) ? reinterpret_cast<const float4*>(Ap)[row * 32 + lane]
                           : make_float4(0.f, 0.f, 0.f, 0.f);
    }
    float4 acc[R];
#pragma unroll
    for (int r = 0; r < R; r++) acc[r] = make_float4(0.f, 0.f, 0.f, 0.f);

    const float4* W4 = reinterpret_cast<const float4*>(W);
#pragma unroll 4
    for (int kk = 0; kk < 32; kk++) {
        float4 w0 = __ldg(W4 + (kk * 4 + 0) * 32 + lane);
        float4 w1 = __ldg(W4 + (kk * 4 + 1) * 32 + lane);
        float4 w2 = __ldg(W4 + (kk * 4 + 2) * 32 + lane);
        float4 w3 = __ldg(W4 + (kk * 4 + 3) * 32 + lane);
#pragma unroll
        for (int r = 0; r < R; r++) {
            float x0 = __shfl_sync(0xffffffffu, xv[r].x, kk);
            float x1 = __shfl_sync(0xffffffffu, xv[r].y, kk);
            float x2 = __shfl_sync(0xffffffffu, xv[r].z, kk);
            float x3 = __shfl_sync(0xffffffffu, xv[r].w, kk);
            acc[r].x += x0 * w0.x + x1 * w1.x + x2 * w2.x + x3 * w3.x;
            acc[r].y += x0 * w0.y + x1 * w1.y + x2 * w2.y + x3 * w3.y;
            acc[r].z += x0 * w0.z + x1 * w1.z + x2 * w2.z + x3 * w3.z;
            acc[r].w += x0 * w0.w + x1 * w1.w + x2 * w2.w + x3 * w3.w;
        }
    }
#pragma unroll
    for (int r = 0; r < R; r++) {
        int row = rowBase + r;
        if (row < NN) reinterpret_cast<float4*>(g_h)[row * 32 + lane] = acc[r];
    }
}

// ---------------- gather-aggregate + self loop + bias + relu ---------------
// one warp per node; lanes own the 128 features as float4
__global__ void k_gather(const float* __restrict__ b) {
    const int lane = threadIdx.x & 31;
    int node = blockIdx.x * (blockDim.x >> 5) + (threadIdx.x >> 5);
    if (node >= NN) return;

    const float4* h4 = reinterpret_cast<const float4*>(g_h);
    float dn = g_dinv[node];

    // self-loop contribution: h[node] * dinv[node]^2
    float4 acc = h4[node * 32 + lane];
    float dd = dn * dn;
    acc.x *= dd; acc.y *= dd; acc.z *= dd; acc.w *= dd;

    int beg = g_row[node];
    int cnt = g_cnt[node];
    for (int j0 = 0; j0 < cnt; j0 += 32) {
        int n = min(32, cnt - j0);
        int s = 0; float w = 0.f;
        if (lane < n) {
            s = g_csr[beg + j0 + lane];
            w = g_dinv[s] * dn;
        }
        for (int i = 0; i < n; i++) {
            int   si = __shfl_sync(0xffffffffu, s, i);
            float wi = __shfl_sync(0xffffffffu, w, i);
            float4 v = h4[si * 32 + lane];
            acc.x += v.x * wi; acc.y += v.y * wi;
            acc.z += v.z * wi; acc.w += v.w * wi;
        }
    }

    float4 bb = reinterpret_cast<const float4*>(b)[lane];
    acc.x = fmaxf(acc.x + bb.x, 0.f);
    acc.y = fmaxf(acc.y + bb.y, 0.f);
    acc.z = fmaxf(acc.z + bb.z, 0.f);
    acc.w = fmaxf(acc.w + bb.w, 0.f);
    reinterpret_cast<float4*>(g_agg)[node * 32 + lane] = acc;
}

// ---------------- final FC: out[N,21] = g_agg @ Wfc + bfc ------------------
__global__ void k_fc(const float* __restrict__ Wfc, const float* __restrict__ bfc,
                     float* __restrict__ out) {
    __shared__ float WsT[NC * HID];  // [c][k]
    __shared__ float bs[NC];
    for (int i = threadIdx.x; i < NC * HID; i += blockDim.x) {
        int c = i >> 7;
        int k = i & 127;
        WsT[i] = Wfc[k * NC + c];
    }
    if (threadIdx.x < NC) bs[threadIdx.x] = bfc[threadIdx.x];
    __syncthreads();

    int lane = threadIdx.x & 31;
    int row = blockIdx.x * (blockDim.x >> 5) + (threadIdx.x >> 5);
    if (row >= NN) return;
    float4 a = reinterpret_cast<const float4*>(g_agg)[row * 32 + lane];
#pragma unroll
    for (int c = 0; c < NC; c++) {
        const float4 w = reinterpret_cast<const float4*>(WsT + c * HID)[lane];
        float p = a.x * w.x + a.y * w.y + a.z * w.z + a.w * w.w;
        p += __shfl_xor_sync(0xffffffffu, p, 16);
        p += __shfl_xor_sync(0xffffffffu, p, 8);
        p += __shfl_xor_sync(0xffffffffu, p, 4);
        p += __shfl_xor_sync(0xffffffffu, p, 2);
        p += __shfl_xor_sync(0xffffffffu, p, 1);
        if (lane == 0) out[row * NC + c] = p + bs[c];
    }
}

// ---------------- launch ----------------
extern "C" void kernel_launch(void* const* d_in, const int* in_sizes, int n_in,
                              void* d_out, int out_size) {
    const float* x  = (const float*)d_in[0];
    const int* ei   = (const int*)d_in[1];   // int32 (JAX x64 disabled)
    const float* W1 = (const float*)d_in[2];
    const float* b1 = (const float*)d_in[3];
    const float* W2 = (const float*)d_in[4];
    const float* b2 = (const float*)d_in[5];
    const float* Wfc = (const float*)d_in[6];
    const float* bfc = (const float*)d_in[7];
    float* out = (float*)d_out;

    const int T = 256;
    const int nBlk = (NN + T - 1) / T;
    const int eBlk = (EE + T - 1) / T;

    // --- graph structure (CSR by destination) ---
    k_init<<<nBlk, T>>>();
    k_deg_count<<<eBlk, T>>>(ei);
    k_dinv<<<nBlk, T>>>();
    k_scan1<<<NB, SCAN_T>>>();
    k_scan2<<<1, 32>>>();
    k_scan3<<<nBlk, T>>>();
    k_bin<<<eBlk, T>>>(ei);

    const int gemmBlocks = (NN + 31) / 32;   // 8 warps * 4 rows per block
    const int warpBlocks = (NN + 7) / 8;     // warp per node/row, 8 warps/block

    // --- conv1: h = x @ W1 ; agg = relu(norm-aggregate + b1) ---
    k_gemm128<<<gemmBlocks, T>>>(x, W1);
    k_gather<<<warpBlocks, T>>>(b1);

    // --- conv2: h = agg @ W2 ; agg = relu(norm-aggregate + b2) ---
    k_gemm128<<<gemmBlocks, T>>>(nullptr, W2);
    k_gather<<<warpBlocks, T>>>(b2);

    // --- fc ---
    k_fc<<<warpBlocks, T>>>(Wfc, bfc, out);
}

// round 4
// speedup vs baseline: 1.1431x; 1.1431x over previous
#include <cuda_runtime.h>
#include <cuda_bf16.h>
#include <cstdint>

#define NN 50000
#define EE 600000
#define HID 128
#define NC 21
#define SCAN_T 512
#define NB ((NN + SCAN_T - 1) / SCAN_T)   // 98

// ---------------- scratch (__device__ globals; no cudaMalloc allowed) ------
__device__ __align__(16) float g_h[NN * HID];     // linear-transform output
__device__ __align__(16) float g_agg[NN * HID];   // conv output (post bias+relu)
__device__ float g_dinv[NN];
__device__ int   g_cnt[NN];      // in-degree (without self loop)
__device__ int   g_cur[NN];      // binning cursor
__device__ int   g_rowinc[NN];   // inclusive block-scan
__device__ int   g_row[NN];      // CSR row start (exclusive scan)
__device__ int   g_bsum[NB];     // per-block scan totals
__device__ int   g_csr[EE];      // src node per CSR slot

// ---------------- init: zero counters ----------------
__global__ void k_init() {
    int i = blockIdx.x * blockDim.x + threadIdx.x;
    if (i < NN) { g_cnt[i] = 0; g_cur[i] = 0; }
}

// edge_index is int32 on device (JAX x64 disabled downcasts int64 -> int32)
__global__ void k_deg_count(const int* __restrict__ ei) {
    int e = blockIdx.x * blockDim.x + threadIdx.x;
    if (e < EE) atomicAdd(&g_cnt[ei[EE + e]], 1);
}

__global__ void k_dinv() {
    int i = blockIdx.x * blockDim.x + threadIdx.x;
    if (i < NN) g_dinv[i] = rsqrtf((float)(g_cnt[i] + 1));
}

// ---------------- 3-kernel exclusive prefix scan of g_cnt -> g_row ---------
__global__ void k_scan1() {
    __shared__ int sh[SCAN_T];
    int gid = blockIdx.x * SCAN_T + threadIdx.x;
    int v = (gid < NN) ? g_cnt[gid] : 0;
    sh[threadIdx.x] = v;
    __syncthreads();
#pragma unroll
    for (int off = 1; off < SCAN_T; off <<= 1) {
        int t = (threadIdx.x >= off) ? sh[threadIdx.x - off] : 0;
        __syncthreads();
        sh[threadIdx.x] += t;
        __syncthreads();
    }
    if (gid < NN) g_rowinc[gid] = sh[threadIdx.x];
    if (threadIdx.x == SCAN_T - 1) g_bsum[blockIdx.x] = sh[threadIdx.x];
}

__global__ void k_scan2() {
    if (blockIdx.x == 0 && threadIdx.x == 0) {
        int acc = 0;
        for (int i = 0; i < NB; i++) { int t = g_bsum[i]; g_bsum[i] = acc; acc += t; }
    }
}

__global__ void k_scan3() {
    int gid = blockIdx.x * blockDim.x + threadIdx.x;
    if (gid < NN)
        g_row[gid] = g_rowinc[gid] - g_cnt[gid] + g_bsum[gid / SCAN_T];
}

// ---------------- bin edges into CSR slots ----------------
__global__ void k_bin(const int* __restrict__ ei) {
    int e = blockIdx.x * blockDim.x + threadIdx.x;
    if (e >= EE) return;
    int s = ei[e];
    int d = ei[EE + e];
    int pos = g_row[d] + atomicAdd(&g_cur[d], 1);
    g_csr[pos] = s;
}

// ---------------- tensor-core GEMM (3xTF32): g_h = A @ W -------------------
// block: 128 rows x 128 cols; 8 warps, each 32 rows x 64 cols
// K chunked by 32 through smem; mma.sync.m16n8k8.tf32 fragments loaded manually
#define BM 128
#define KC 32
#define SWS 132   // W smem stride (conflict-free for B-frag pattern)
#define SAS 36    // A smem stride (conflict-free for A-frag pattern)

__device__ __forceinline__ void tf32_split(float v, uint32_t& hi, uint32_t& lo) {
    asm("cvt.rna.tf32.f32 %0, %1;" : "=r"(hi) : "f"(v));
    float r = v - __uint_as_float(hi);
    asm("cvt.rna.tf32.f32 %0, %1;" : "=r"(lo) : "f"(r));
}

__device__ __forceinline__ void mma_tf32(float* d, const uint32_t* a, const uint32_t* b) {
    asm volatile(
        "mma.sync.aligned.m16n8k8.row.col.f32.tf32.tf32.f32 "
        "{%0,%1,%2,%3}, {%4,%5,%6,%7}, {%8,%9}, {%0,%1,%2,%3};"
        : "+f"(d[0]), "+f"(d[1]), "+f"(d[2]), "+f"(d[3])
        : "r"(a[0]), "r"(a[1]), "r"(a[2]), "r"(a[3]), "r"(b[0]), "r"(b[1]));
}

__global__ __launch_bounds__(256) void k_gemm_tc(const float* __restrict__ A,
                                                 const float* __restrict__ W) {
    const float* Ap = A ? A : g_agg;
    __shared__ float sW[KC * SWS];
    __shared__ float sA[BM * SAS];

    const int tid  = threadIdx.x;
    const int lane = tid & 31;
    const int warp = tid >> 5;
    const int wm = warp >> 1;          // 0..3 -> rows 32*wm
    const int wn = warp & 1;           // 0..1 -> cols 64*wn
    const int gid = lane >> 2;         // 0..7
    const int tig = lane & 3;          // 0..3
    const int rowBase = blockIdx.x * BM;

    float acc[2][8][4];
#pragma unroll
    for (int mt = 0; mt < 2; mt++)
#pragma unroll
        for (int nt = 0; nt < 8; nt++)
#pragma unroll
            for (int q = 0; q < 4; q++) acc[mt][nt][q] = 0.f;

    for (int kc = 0; kc < HID; kc += KC) {
        __syncthreads();
        // load W chunk [KC][128]
#pragma unroll
        for (int i = 0; i < 4; i++) {
            int idx = i * 256 + tid;        // 1024 float4s
            int r = idx >> 5, cq = idx & 31;
            float4 v = *reinterpret_cast<const float4*>(W + (kc + r) * HID + cq * 4);
            *reinterpret_cast<float4*>(sW + r * SWS + cq * 4) = v;
        }
        // load A chunk [128][KC]
#pragma unroll
        for (int i = 0; i < 4; i++) {
            int idx = i * 256 + tid;        // 1024 float4s (128 rows x 8)
            int r = idx >> 3, kq = idx & 7;
            int grow = rowBase + r;
            float4 v = (grow < NN)
                ? *reinterpret_cast<const float4*>(Ap + grow * HID + kc + kq * 4)
                : make_float4(0.f, 0.f, 0.f, 0.f);
            *reinterpret_cast<float4*>(sA + r * SAS + kq * 4) = v;
        }
        __syncthreads();

#pragma unroll
        for (int ks = 0; ks < KC; ks += 8) {
            uint32_t ah[2][4], al[2][4];
#pragma unroll
            for (int mt = 0; mt < 2; mt++) {
                int r0 = wm * 32 + mt * 16;
#pragma unroll
                for (int q = 0; q < 4; q++) {
                    int rr = r0 + gid + (q & 1) * 8;
                    int kk = ks + tig + (q >> 1) * 4;
                    tf32_split(sA[rr * SAS + kk], ah[mt][q], al[mt][q]);
                }
            }
            uint32_t bh[8][2], bl[8][2];
#pragma unroll
            for (int nt = 0; nt < 8; nt++) {
                int c0 = wn * 64 + nt * 8 + gid;
#pragma unroll
                for (int q = 0; q < 2; q++) {
                    int kk = ks + tig + q * 4;
                    tf32_split(sW[kk * SWS + c0], bh[nt][q], bl[nt][q]);
                }
            }
#pragma unroll
            for (int mt = 0; mt < 2; mt++)
#pragma unroll
                for (int nt = 0; nt < 8; nt++) {
                    mma_tf32(acc[mt][nt], ah[mt], bh[nt]);
                    mma_tf32(acc[mt][nt], al[mt], bh[nt]);
                    mma_tf32(acc[mt][nt], ah[mt], bl[nt]);
                }
        }
    }

    // epilogue: c0/c1 -> (row, 2*tig), c2/c3 -> (row+8, 2*tig)
#pragma unroll
    for (int mt = 0; mt < 2; mt++) {
        int r0 = rowBase + wm * 32 + mt * 16 + gid;
#pragma unroll
        for (int half = 0; half < 2; half++) {
            int row = r0 + half * 8;
            if (row < NN) {
#pragma unroll
                for (int nt = 0; nt < 8; nt++) {
                    int col = wn * 64 + nt * 8 + tig * 2;
                    *reinterpret_cast<float2*>(g_h + row * HID + col) =
                        make_float2(acc[mt][nt][half * 2], acc[mt][nt][half * 2 + 1]);
                }
            }
        }
    }
}

// ---------------- gather-aggregate + self loop + bias + relu ---------------
__global__ void k_gather(const float* __restrict__ b) {
    const int lane = threadIdx.x & 31;
    int node = blockIdx.x * (blockDim.x >> 5) + (threadIdx.x >> 5);
    if (node >= NN) return;

    const float4* h4 = reinterpret_cast<const float4*>(g_h);
    float dn = g_dinv[node];

    float4 acc = h4[node * 32 + lane];
    float dd = dn * dn;
    acc.x *= dd; acc.y *= dd; acc.z *= dd; acc.w *= dd;

    int beg = g_row[node];
    int cnt = g_cnt[node];
    for (int j0 = 0; j0 < cnt; j0 += 32) {
        int n = min(32, cnt - j0);
        int s = 0; float w = 0.f;
        if (lane < n) {
            s = g_csr[beg + j0 + lane];
            w = g_dinv[s] * dn;
        }
        for (int i = 0; i < n; i++) {
            int   si = __shfl_sync(0xffffffffu, s, i);
            float wi = __shfl_sync(0xffffffffu, w, i);
            float4 v = h4[si * 32 + lane];
            acc.x += v.x * wi; acc.y += v.y * wi;
            acc.z += v.z * wi; acc.w += v.w * wi;
        }
    }

    float4 bb = reinterpret_cast<const float4*>(b)[lane];
    acc.x = fmaxf(acc.x + bb.x, 0.f);
    acc.y = fmaxf(acc.y + bb.y, 0.f);
    acc.z = fmaxf(acc.z + bb.z, 0.f);
    acc.w = fmaxf(acc.w + bb.w, 0.f);
    reinterpret_cast<float4*>(g_agg)[node * 32 + lane] = acc;
}

// ---------------- final FC: out[N,21] = g_agg @ Wfc + bfc ------------------
__global__ void k_fc(const float* __restrict__ Wfc, const float* __restrict__ bfc,
                     float* __restrict__ out) {
    __shared__ float WsT[NC * HID];  // [c][k]
    __shared__ float bs[NC];
    for (int i = threadIdx.x; i < NC * HID; i += blockDim.x) {
        int c = i >> 7;
        int k = i & 127;
        WsT[i] = Wfc[k * NC + c];
    }
    if (threadIdx.x < NC) bs[threadIdx.x] = bfc[threadIdx.x];
    __syncthreads();

    int lane = threadIdx.x & 31;
    int row = blockIdx.x * (blockDim.x >> 5) + (threadIdx.x >> 5);
    if (row >= NN) return;
    float4 a = reinterpret_cast<const float4*>(g_agg)[row * 32 + lane];
#pragma unroll
    for (int c = 0; c < NC; c++) {
        const float4 w = reinterpret_cast<const float4*>(WsT + c * HID)[lane];
        float p = a.x * w.x + a.y * w.y + a.z * w.z + a.w * w.w;
        p += __shfl_xor_sync(0xffffffffu, p, 16);
        p += __shfl_xor_sync(0xffffffffu, p, 8);
        p += __shfl_xor_sync(0xffffffffu, p, 4);
        p += __shfl_xor_sync(0xffffffffu, p, 2);
        p += __shfl_xor_sync(0xffffffffu, p, 1);
        if (lane == 0) out[row * NC + c] = p + bs[c];
    }
}

// ---------------- launch ----------------
extern "C" void kernel_launch(void* const* d_in, const int* in_sizes, int n_in,
                              void* d_out, int out_size) {
    const float* x  = (const float*)d_in[0];
    const int* ei   = (const int*)d_in[1];   // int32 (JAX x64 disabled)
    const float* W1 = (const float*)d_in[2];
    const float* b1 = (const float*)d_in[3];
    const float* W2 = (const float*)d_in[4];
    const float* b2 = (const float*)d_in[5];
    const float* Wfc = (const float*)d_in[6];
    const float* bfc = (const float*)d_in[7];
    float* out = (float*)d_out;

    const int T = 256;
    const int nBlk = (NN + T - 1) / T;
    const int eBlk = (EE + T - 1) / T;

    // --- graph structure (CSR by destination) ---
    k_init<<<nBlk, T>>>();
    k_deg_count<<<eBlk, T>>>(ei);
    k_dinv<<<nBlk, T>>>();
    k_scan1<<<NB, SCAN_T>>>();
    k_scan2<<<1, 32>>>();
    k_scan3<<<nBlk, T>>>();
    k_bin<<<eBlk, T>>>(ei);

    const int gemmBlocks = (NN + BM - 1) / BM;   // 391
    const int warpBlocks = (NN + 7) / 8;         // warp per node/row

    // --- conv1 ---
    k_gemm_tc<<<gemmBlocks, 256>>>(x, W1);
    k_gather<<<warpBlocks, T>>>(b1);

    // --- conv2 ---
    k_gemm_tc<<<gemmBlocks, 256>>>(nullptr, W2);
    k_gather<<<warpBlocks, T>>>(b2);

    // --- fc ---
    k_fc<<<warpBlocks, T>>>(Wfc, bfc, out);
}

// round 5
// speedup vs baseline: 1.1801x; 1.0324x over previous
#include <cuda_runtime.h>
#include <cuda_bf16.h>
#include <cstdint>

#define NN 50000
#define EE 600000
#define HID 128
#define NC 21
#define SCAN_T 512
#define NB ((NN + SCAN_T - 1) / SCAN_T)   // 98

// ---------------- scratch (__device__ globals; no cudaMalloc allowed) ------
__device__ __align__(16) float g_h[NN * HID];     // linear-transform output
__device__ __align__(16) float g_agg[NN * HID];   // conv output (post bias+relu)
__device__ float g_dinv[NN];
__device__ int   g_cnt[NN];      // in-degree (without self loop)
__device__ int   g_cur[NN];      // binning cursor
__device__ int   g_rowinc[NN];   // inclusive block-scan
__device__ int   g_row[NN];      // CSR row start (exclusive scan)
__device__ int   g_bsum[NB];     // per-block scan totals
__device__ int   g_csr[EE];      // src node per CSR slot
__device__ float g_wgt[EE];      // dinv[s]*dinv[d] per CSR slot

// ---------------- init: zero degree counters ----------------
__global__ void k_init() {
    int i = blockIdx.x * blockDim.x + threadIdx.x;
    if (i < NN) g_cnt[i] = 0;
}

// edge_index is int32 on device (JAX x64 disabled downcasts int64 -> int32)
__global__ void k_deg_count(const int* __restrict__ ei) {
    int e = blockIdx.x * blockDim.x + threadIdx.x;
    if (e < EE) atomicAdd(&g_cnt[ei[EE + e]], 1);
}

// ---------------- 3-kernel exclusive prefix scan of g_cnt -> g_row ---------
__global__ void k_scan1() {
    __shared__ int sh[SCAN_T];
    int gid = blockIdx.x * SCAN_T + threadIdx.x;
    int v = (gid < NN) ? g_cnt[gid] : 0;
    sh[threadIdx.x] = v;
    __syncthreads();
#pragma unroll
    for (int off = 1; off < SCAN_T; off <<= 1) {
        int t = (threadIdx.x >= off) ? sh[threadIdx.x - off] : 0;
        __syncthreads();
        sh[threadIdx.x] += t;
        __syncthreads();
    }
    if (gid < NN) g_rowinc[gid] = sh[threadIdx.x];
    if (threadIdx.x == SCAN_T - 1) g_bsum[blockIdx.x] = sh[threadIdx.x];
}

__global__ void k_scan2() {
    if (blockIdx.x == 0 && threadIdx.x == 0) {
        int acc = 0;
        for (int i = 0; i < NB; i++) { int t = g_bsum[i]; g_bsum[i] = acc; acc += t; }
    }
}

// scan3 fused with dinv + cursor zeroing
__global__ void k_scan3() {
    int gid = blockIdx.x * blockDim.x + threadIdx.x;
    if (gid < NN) {
        int c = g_cnt[gid];
        g_row[gid] = g_rowinc[gid] - c + g_bsum[gid / SCAN_T];
        g_dinv[gid] = rsqrtf((float)(c + 1));
        g_cur[gid] = 0;
    }
}

// ---------------- bin edges into CSR slots (+ edge weight) ----------------
__global__ void k_bin(const int* __restrict__ ei) {
    int e = blockIdx.x * blockDim.x + threadIdx.x;
    if (e >= EE) return;
    int s = ei[e];
    int d = ei[EE + e];
    int pos = g_row[d] + atomicAdd(&g_cur[d], 1);
    g_csr[pos] = s;
    g_wgt[pos] = g_dinv[s] * g_dinv[d];
}

// ---------------- tensor-core GEMM (3xTF32, pre-split smem) ----------------
// block: 128 rows x 128 cols; 8 warps each 32x64; K chunked by 16
#define BM 128
#define KC 16
#define SWS 136   // W smem stride: 8*tig+gid banks all distinct -> conflict-free
#define SAS 20    // A smem stride: verified conflict-free for A-frag pattern

__device__ __forceinline__ void tf32_split(float v, uint32_t& hi, uint32_t& lo) {
    asm("cvt.rna.tf32.f32 %0, %1;" : "=r"(hi) : "f"(v));
    float r = v - __uint_as_float(hi);
    asm("cvt.rna.tf32.f32 %0, %1;" : "=r"(lo) : "f"(r));
}

__device__ __forceinline__ void mma_tf32(float* d, const uint32_t* a, const uint32_t* b) {
    asm volatile(
        "mma.sync.aligned.m16n8k8.row.col.f32.tf32.tf32.f32 "
        "{%0,%1,%2,%3}, {%4,%5,%6,%7}, {%8,%9}, {%0,%1,%2,%3};"
        : "+f"(d[0]), "+f"(d[1]), "+f"(d[2]), "+f"(d[3])
        : "r"(a[0]), "r"(a[1]), "r"(a[2]), "r"(a[3]), "r"(b[0]), "r"(b[1]));
}

__global__ __launch_bounds__(256) void k_gemm_tc(const float* __restrict__ A,
                                                 const float* __restrict__ W) {
    const float* Ap = A ? A : g_agg;
    __shared__ uint32_t sWh[KC * SWS], sWl[KC * SWS];
    __shared__ uint32_t sAh[BM * SAS], sAl[BM * SAS];

    const int tid  = threadIdx.x;
    const int lane = tid & 31;
    const int warp = tid >> 5;
    const int wm = warp >> 1;          // 0..3 -> rows 32*wm
    const int wn = warp & 1;           // 0..1 -> cols 64*wn
    const int gid = lane >> 2;         // 0..7
    const int tig = lane & 3;          // 0..3
    const int rowBase = blockIdx.x * BM;

    float acc[2][8][4];
#pragma unroll
    for (int mt = 0; mt < 2; mt++)
#pragma unroll
        for (int nt = 0; nt < 8; nt++)
#pragma unroll
            for (int q = 0; q < 4; q++) acc[mt][nt][q] = 0.f;

    for (int kc = 0; kc < HID; kc += KC) {
        __syncthreads();
        // load + split W chunk [KC][128]: 512 float4s, 2 per thread
#pragma unroll
        for (int i = 0; i < 2; i++) {
            int idx = i * 256 + tid;
            int r = idx >> 5, cq = idx & 31;
            float4 v = *reinterpret_cast<const float4*>(W + (kc + r) * HID + cq * 4);
            uint4 hi, lo;
            tf32_split(v.x, hi.x, lo.x); tf32_split(v.y, hi.y, lo.y);
            tf32_split(v.z, hi.z, lo.z); tf32_split(v.w, hi.w, lo.w);
            *reinterpret_cast<uint4*>(sWh + r * SWS + cq * 4) = hi;
            *reinterpret_cast<uint4*>(sWl + r * SWS + cq * 4) = lo;
        }
        // load + split A chunk [128][KC]: 512 float4s, 2 per thread
#pragma unroll
        for (int i = 0; i < 2; i++) {
            int idx = i * 256 + tid;
            int r = idx >> 2, kq = idx & 3;
            int grow = rowBase + r;
            float4 v = (grow < NN)
                ? *reinterpret_cast<const float4*>(Ap + grow * HID + kc + kq * 4)
                : make_float4(0.f, 0.f, 0.f, 0.f);
            uint4 hi, lo;
            tf32_split(v.x, hi.x, lo.x); tf32_split(v.y, hi.y, lo.y);
            tf32_split(v.z, hi.z, lo.z); tf32_split(v.w, hi.w, lo.w);
            *reinterpret_cast<uint4*>(sAh + r * SAS + kq * 4) = hi;
            *reinterpret_cast<uint4*>(sAl + r * SAS + kq * 4) = lo;
        }
        __syncthreads();

#pragma unroll
        for (int ks = 0; ks < KC; ks += 8) {
            uint32_t ah[2][4], al[2][4];
#pragma unroll
            for (int mt = 0; mt < 2; mt++) {
                int r0 = wm * 32 + mt * 16;
#pragma unroll
                for (int q = 0; q < 4; q++) {
                    int rr = r0 + gid + (q & 1) * 8;
                    int kk = ks + tig + (q >> 1) * 4;
                    ah[mt][q] = sAh[rr * SAS + kk];
                    al[mt][q] = sAl[rr * SAS + kk];
                }
            }
#pragma unroll
            for (int nt = 0; nt < 8; nt++) {
                int c0 = wn * 64 + nt * 8 + gid;
                uint32_t bh[2], bl[2];
#pragma unroll
                for (int q = 0; q < 2; q++) {
                    int kk = ks + tig + q * 4;
                    bh[q] = sWh[kk * SWS + c0];
                    bl[q] = sWl[kk * SWS + c0];
                }
#pragma unroll
                for (int mt = 0; mt < 2; mt++) {
                    mma_tf32(acc[mt][nt], ah[mt], bh);
                    mma_tf32(acc[mt][nt], al[mt], bh);
                    mma_tf32(acc[mt][nt], ah[mt], bl);
                }
            }
        }
    }

    // epilogue: c0/c1 -> (row, 2*tig), c2/c3 -> (row+8, 2*tig)
#pragma unroll
    for (int mt = 0; mt < 2; mt++) {
        int r0 = rowBase + wm * 32 + mt * 16 + gid;
#pragma unroll
        for (int half = 0; half < 2; half++) {
            int row = r0 + half * 8;
            if (row < NN) {
#pragma unroll
                for (int nt = 0; nt < 8; nt++) {
                    int col = wn * 64 + nt * 8 + tig * 2;
                    *reinterpret_cast<float2*>(g_h + row * HID + col) =
                        make_float2(acc[mt][nt][half * 2], acc[mt][nt][half * 2 + 1]);
                }
            }
        }
    }
}

// ---------------- gather-aggregate + self loop + bias + relu ---------------
__global__ void k_gather(const float* __restrict__ b) {
    const int lane = threadIdx.x & 31;
    int node = blockIdx.x * (blockDim.x >> 5) + (threadIdx.x >> 5);
    if (node >= NN) return;

    const float4* h4 = reinterpret_cast<const float4*>(g_h);
    float dn = g_dinv[node];

    float4 acc = h4[node * 32 + lane];
    float dd = dn * dn;
    acc.x *= dd; acc.y *= dd; acc.z *= dd; acc.w *= dd;

    int beg = g_row[node];
    int cnt = g_cnt[node];
    for (int j0 = 0; j0 < cnt; j0 += 32) {
        int n = min(32, cnt - j0);
        int s = 0; float w = 0.f;
        if (lane < n) {
            s = g_csr[beg + j0 + lane];
            w = g_wgt[beg + j0 + lane];
        }
        for (int i = 0; i < n; i++) {
            int   si = __shfl_sync(0xffffffffu, s, i);
            float wi = __shfl_sync(0xffffffffu, w, i);
            float4 v = h4[si * 32 + lane];
            acc.x += v.x * wi; acc.y += v.y * wi;
            acc.z += v.z * wi; acc.w += v.w * wi;
        }
    }

    float4 bb = reinterpret_cast<const float4*>(b)[lane];
    acc.x = fmaxf(acc.x + bb.x, 0.f);
    acc.y = fmaxf(acc.y + bb.y, 0.f);
    acc.z = fmaxf(acc.z + bb.z, 0.f);
    acc.w = fmaxf(acc.w + bb.w, 0.f);
    reinterpret_cast<float4*>(g_agg)[node * 32 + lane] = acc;
}

// ---------------- final FC: out[N,21] = g_agg @ Wfc + bfc ------------------
__global__ void k_fc(const float* __restrict__ Wfc, const float* __restrict__ bfc,
                     float* __restrict__ out) {
    __shared__ float WsT[NC * HID];  // [c][k]
    __shared__ float bs[NC];
    for (int i = threadIdx.x; i < NC * HID; i += blockDim.x) {
        int c = i >> 7;
        int k = i & 127;
        WsT[i] = Wfc[k * NC + c];
    }
    if (threadIdx.x < NC) bs[threadIdx.x] = bfc[threadIdx.x];
    __syncthreads();

    int lane = threadIdx.x & 31;
    int row = blockIdx.x * (blockDim.x >> 5) + (threadIdx.x >> 5);
    if (row >= NN) return;
    float4 a = reinterpret_cast<const float4*>(g_agg)[row * 32 + lane];
#pragma unroll
    for (int c = 0; c < NC; c++) {
        const float4 w = reinterpret_cast<const float4*>(WsT + c * HID)[lane];
        float p = a.x * w.x + a.y * w.y + a.z * w.z + a.w * w.w;
        p += __shfl_xor_sync(0xffffffffu, p, 16);
        p += __shfl_xor_sync(0xffffffffu, p, 8);
        p += __shfl_xor_sync(0xffffffffu, p, 4);
        p += __shfl_xor_sync(0xffffffffu, p, 2);
        p += __shfl_xor_sync(0xffffffffu, p, 1);
        if (lane == 0) out[row * NC + c] = p + bs[c];
    }
}

// ---------------- launch ----------------
extern "C" void kernel_launch(void* const* d_in, const int* in_sizes, int n_in,
                              void* d_out, int out_size) {
    const float* x  = (const float*)d_in[0];
    const int* ei   = (const int*)d_in[1];   // int32 (JAX x64 disabled)
    const float* W1 = (const float*)d_in[2];
    const float* b1 = (const float*)d_in[3];
    const float* W2 = (const float*)d_in[4];
    const float* b2 = (const float*)d_in[5];
    const float* Wfc = (const float*)d_in[6];
    const float* bfc = (const float*)d_in[7];
    float* out = (float*)d_out;

    const int T = 256;
    const int nBlk = (NN + T - 1) / T;
    const int eBlk = (EE + T - 1) / T;

    // --- graph structure (CSR by destination, with edge weights) ---
    k_init<<<nBlk, T>>>();
    k_deg_count<<<eBlk, T>>>(ei);
    k_scan1<<<NB, SCAN_T>>>();
    k_scan2<<<1, 32>>>();
    k_scan3<<<nBlk, T>>>();
    k_bin<<<eBlk, T>>>(ei);

    const int gemmBlocks = (NN + BM - 1) / BM;   // 391
    const int warpBlocks = (NN + 7) / 8;         // warp per node/row

    // --- conv1 ---
    k_gemm_tc<<<gemmBlocks, 256>>>(x, W1);
    k_gather<<<warpBlocks, T>>>(b1);

    // --- conv2 ---
    k_gemm_tc<<<gemmBlocks, 256>>>(nullptr, W2);
    k_gather<<<warpBlocks, T>>>(b2);

    // --- fc ---
    k_fc<<<warpBlocks, T>>>(Wfc, bfc, out);
}

// round 6
// speedup vs baseline: 1.2519x; 1.0609x over previous
#include <cuda_runtime.h>
#include <cuda_fp16.h>
#include <cstdint>

#define NN 50000
#define EE 600000
#define HID 128
#define NC 21
#define SCAN_T 512
#define NB ((NN + SCAN_T - 1) / SCAN_T)   // 98

// ---------------- scratch (__device__ globals; no cudaMalloc allowed) ------
__device__ __align__(16) __half g_h[NN * HID];    // linear-transform output (fp16)
__device__ __align__(16) float g_agg[NN * HID];   // conv output (post bias+relu)
__device__ float g_dinv[NN];
__device__ int   g_cnt[NN];      // in-degree (without self loop)
__device__ int   g_cur[NN];      // binning cursor
__device__ int   g_rowinc[NN];   // inclusive block-scan
__device__ int   g_row[NN];      // CSR row start (exclusive scan)
__device__ int   g_bsum[NB];     // per-block scan totals
__device__ int   g_csr[EE];      // src node per CSR slot
__device__ float g_wgt[EE];      // dinv[s]*dinv[d] per CSR slot

// ---------------- init: zero degree counters ----------------
__global__ void k_init() {
    int i = blockIdx.x * blockDim.x + threadIdx.x;
    if (i < NN) g_cnt[i] = 0;
}

// edge_index is int32 on device (JAX x64 disabled downcasts int64 -> int32)
__global__ void k_deg_count(const int* __restrict__ ei) {
    int e = blockIdx.x * blockDim.x + threadIdx.x;
    if (e < EE) atomicAdd(&g_cnt[ei[EE + e]], 1);
}

// ---------------- 3-kernel exclusive prefix scan of g_cnt -> g_row ---------
__global__ void k_scan1() {
    __shared__ int sh[SCAN_T];
    int gid = blockIdx.x * SCAN_T + threadIdx.x;
    int v = (gid < NN) ? g_cnt[gid] : 0;
    sh[threadIdx.x] = v;
    __syncthreads();
#pragma unroll
    for (int off = 1; off < SCAN_T; off <<= 1) {
        int t = (threadIdx.x >= off) ? sh[threadIdx.x - off] : 0;
        __syncthreads();
        sh[threadIdx.x] += t;
        __syncthreads();
    }
    if (gid < NN) g_rowinc[gid] = sh[threadIdx.x];
    if (threadIdx.x == SCAN_T - 1) g_bsum[blockIdx.x] = sh[threadIdx.x];
}

// warp shfl-scan over the 98 block sums (was a serial 1-thread loop)
__global__ void k_scan2() {
    int lane = threadIdx.x;
    int carry = 0;
    for (int base = 0; base < NB; base += 32) {
        int i = base + lane;
        int v = (i < NB) ? g_bsum[i] : 0;
        int incl = v;
#pragma unroll
        for (int off = 1; off < 32; off <<= 1) {
            int t = __shfl_up_sync(0xffffffffu, incl, off);
            if (lane >= off) incl += t;
        }
        if (i < NB) g_bsum[i] = incl - v + carry;
        carry += __shfl_sync(0xffffffffu, incl, 31);
    }
}

// scan3 fused with dinv + cursor zeroing
__global__ void k_scan3() {
    int gid = blockIdx.x * blockDim.x + threadIdx.x;
    if (gid < NN) {
        int c = g_cnt[gid];
        g_row[gid] = g_rowinc[gid] - c + g_bsum[gid / SCAN_T];
        g_dinv[gid] = rsqrtf((float)(c + 1));
        g_cur[gid] = 0;
    }
}

// ---------------- bin edges into CSR slots (+ edge weight) ----------------
__global__ void k_bin(const int* __restrict__ ei) {
    int e = blockIdx.x * blockDim.x + threadIdx.x;
    if (e >= EE) return;
    int s = ei[e];
    int d = ei[EE + e];
    int pos = g_row[d] + atomicAdd(&g_cur[d], 1);
    g_csr[pos] = s;
    g_wgt[pos] = g_dinv[s] * g_dinv[d];
}

// ---------------- tensor-core GEMM (3xTF32, pre-split smem) ----------------
// block: 128 rows x 128 cols; 8 warps each 32x64; K chunked by 16
#define BM 128
#define KC 16
#define SWS 136
#define SAS 20

__device__ __forceinline__ void tf32_split(float v, uint32_t& hi, uint32_t& lo) {
    asm("cvt.rna.tf32.f32 %0, %1;" : "=r"(hi) : "f"(v));
    float r = v - __uint_as_float(hi);
    asm("cvt.rna.tf32.f32 %0, %1;" : "=r"(lo) : "f"(r));
}

__device__ __forceinline__ void mma_tf32(float* d, const uint32_t* a, const uint32_t* b) {
    asm volatile(
        "mma.sync.aligned.m16n8k8.row.col.f32.tf32.tf32.f32 "
        "{%0,%1,%2,%3}, {%4,%5,%6,%7}, {%8,%9}, {%0,%1,%2,%3};"
        : "+f"(d[0]), "+f"(d[1]), "+f"(d[2]), "+f"(d[3])
        : "r"(a[0]), "r"(a[1]), "r"(a[2]), "r"(a[3]), "r"(b[0]), "r"(b[1]));
}

__global__ __launch_bounds__(256) void k_gemm_tc(const float* __restrict__ A,
                                                 const float* __restrict__ W) {
    const float* Ap = A ? A : g_agg;
    __shared__ uint32_t sWh[KC * SWS], sWl[KC * SWS];
    __shared__ uint32_t sAh[BM * SAS], sAl[BM * SAS];

    const int tid  = threadIdx.x;
    const int lane = tid & 31;
    const int warp = tid >> 5;
    const int wm = warp >> 1;
    const int wn = warp & 1;
    const int gid = lane >> 2;
    const int tig = lane & 3;
    const int rowBase = blockIdx.x * BM;

    float acc[2][8][4];
#pragma unroll
    for (int mt = 0; mt < 2; mt++)
#pragma unroll
        for (int nt = 0; nt < 8; nt++)
#pragma unroll
            for (int q = 0; q < 4; q++) acc[mt][nt][q] = 0.f;

    for (int kc = 0; kc < HID; kc += KC) {
        __syncthreads();
#pragma unroll
        for (int i = 0; i < 2; i++) {
            int idx = i * 256 + tid;
            int r = idx >> 5, cq = idx & 31;
            float4 v = *reinterpret_cast<const float4*>(W + (kc + r) * HID + cq * 4);
            uint4 hi, lo;
            tf32_split(v.x, hi.x, lo.x); tf32_split(v.y, hi.y, lo.y);
            tf32_split(v.z, hi.z, lo.z); tf32_split(v.w, hi.w, lo.w);
            *reinterpret_cast<uint4*>(sWh + r * SWS + cq * 4) = hi;
            *reinterpret_cast<uint4*>(sWl + r * SWS + cq * 4) = lo;
        }
#pragma unroll
        for (int i = 0; i < 2; i++) {
            int idx = i * 256 + tid;
            int r = idx >> 2, kq = idx & 3;
            int grow = rowBase + r;
            float4 v = (grow < NN)
                ? *reinterpret_cast<const float4*>(Ap + grow * HID + kc + kq * 4)
                : make_float4(0.f, 0.f, 0.f, 0.f);
            uint4 hi, lo;
            tf32_split(v.x, hi.x, lo.x); tf32_split(v.y, hi.y, lo.y);
            tf32_split(v.z, hi.z, lo.z); tf32_split(v.w, hi.w, lo.w);
            *reinterpret_cast<uint4*>(sAh + r * SAS + kq * 4) = hi;
            *reinterpret_cast<uint4*>(sAl + r * SAS + kq * 4) = lo;
        }
        __syncthreads();

#pragma unroll
        for (int ks = 0; ks < KC; ks += 8) {
            uint32_t ah[2][4], al[2][4];
#pragma unroll
            for (int mt = 0; mt < 2; mt++) {
                int r0 = wm * 32 + mt * 16;
#pragma unroll
                for (int q = 0; q < 4; q++) {
                    int rr = r0 + gid + (q & 1) * 8;
                    int kk = ks + tig + (q >> 1) * 4;
                    ah[mt][q] = sAh[rr * SAS + kk];
                    al[mt][q] = sAl[rr * SAS + kk];
                }
            }
#pragma unroll
            for (int nt = 0; nt < 8; nt++) {
                int c0 = wn * 64 + nt * 8 + gid;
                uint32_t bh[2], bl[2];
#pragma unroll
                for (int q = 0; q < 2; q++) {
                    int kk = ks + tig + q * 4;
                    bh[q] = sWh[kk * SWS + c0];
                    bl[q] = sWl[kk * SWS + c0];
                }
#pragma unroll
                for (int mt = 0; mt < 2; mt++) {
                    mma_tf32(acc[mt][nt], ah[mt], bh);
                    mma_tf32(acc[mt][nt], al[mt], bh);
                    mma_tf32(acc[mt][nt], ah[mt], bl);
                }
            }
        }
    }

    // epilogue -> fp16 h; c0/c1 -> (row, 2*tig), c2/c3 -> (row+8, 2*tig)
    __half2* h2 = reinterpret_cast<__half2*>(g_h);
#pragma unroll
    for (int mt = 0; mt < 2; mt++) {
        int r0 = rowBase + wm * 32 + mt * 16 + gid;
#pragma unroll
        for (int half_ = 0; half_ < 2; half_++) {
            int row = r0 + half_ * 8;
            if (row < NN) {
#pragma unroll
                for (int nt = 0; nt < 8; nt++) {
                    int col = wn * 64 + nt * 8 + tig * 2;
                    h2[row * 64 + (col >> 1)] =
                        __floats2half2_rn(acc[mt][nt][half_ * 2], acc[mt][nt][half_ * 2 + 1]);
                }
            }
        }
    }
}

// ---------------- gather-aggregate + self loop + bias + relu ---------------
// one warp per node; lane owns 4 features (one uint2 = 4 halves)
__global__ void k_gather(const float* __restrict__ b) {
    const int lane = threadIdx.x & 31;
    int node = blockIdx.x * (blockDim.x >> 5) + (threadIdx.x >> 5);
    if (node >= NN) return;

    const uint2* h4 = reinterpret_cast<const uint2*>(g_h);  // 32 uint2 per row
    float dn = g_dinv[node];
    float dd = dn * dn;

    uint2 u = h4[node * 32 + lane];
    float2 f0 = __half22float2(*reinterpret_cast<__half2*>(&u.x));
    float2 f1 = __half22float2(*reinterpret_cast<__half2*>(&u.y));
    float4 acc = make_float4(f0.x * dd, f0.y * dd, f1.x * dd, f1.y * dd);

    int beg = g_row[node];
    int cnt = g_cnt[node];
    for (int j0 = 0; j0 < cnt; j0 += 32) {
        int n = min(32, cnt - j0);
        int s = 0; float w = 0.f;
        if (lane < n) {
            s = g_csr[beg + j0 + lane];
            w = g_wgt[beg + j0 + lane];
        }
        for (int i = 0; i < n; i++) {
            int   si = __shfl_sync(0xffffffffu, s, i);
            float wi = __shfl_sync(0xffffffffu, w, i);
            uint2 uv = h4[si * 32 + lane];
            float2 v0 = __half22float2(*reinterpret_cast<__half2*>(&uv.x));
            float2 v1 = __half22float2(*reinterpret_cast<__half2*>(&uv.y));
            acc.x += v0.x * wi; acc.y += v0.y * wi;
            acc.z += v1.x * wi; acc.w += v1.y * wi;
        }
    }

    float4 bb = reinterpret_cast<const float4*>(b)[lane];
    acc.x = fmaxf(acc.x + bb.x, 0.f);
    acc.y = fmaxf(acc.y + bb.y, 0.f);
    acc.z = fmaxf(acc.z + bb.z, 0.f);
    acc.w = fmaxf(acc.w + bb.w, 0.f);
    reinterpret_cast<float4*>(g_agg)[node * 32 + lane] = acc;
}

// ---------------- final FC: out[N,21] = g_agg @ Wfc + bfc ------------------
__global__ void k_fc(const float* __restrict__ Wfc, const float* __restrict__ bfc,
                     float* __restrict__ out) {
    __shared__ float WsT[NC * HID];
    __shared__ float bs[NC];
    for (int i = threadIdx.x; i < NC * HID; i += blockDim.x) {
        int c = i >> 7;
        int k = i & 127;
        WsT[i] = Wfc[k * NC + c];
    }
    if (threadIdx.x < NC) bs[threadIdx.x] = bfc[threadIdx.x];
    __syncthreads();

    int lane = threadIdx.x & 31;
    int row = blockIdx.x * (blockDim.x >> 5) + (threadIdx.x >> 5);
    if (row >= NN) return;
    float4 a = reinterpret_cast<const float4*>(g_agg)[row * 32 + lane];
#pragma unroll
    for (int c = 0; c < NC; c++) {
        const float4 w = reinterpret_cast<const float4*>(WsT + c * HID)[lane];
        float p = a.x * w.x + a.y * w.y + a.z * w.z + a.w * w.w;
        p += __shfl_xor_sync(0xffffffffu, p, 16);
        p += __shfl_xor_sync(0xffffffffu, p, 8);
        p += __shfl_xor_sync(0xffffffffu, p, 4);
        p += __shfl_xor_sync(0xffffffffu, p, 2);
        p += __shfl_xor_sync(0xffffffffu, p, 1);
        if (lane == 0) out[row * NC + c] = p + bs[c];
    }
}

// ---------------- launch ----------------
extern "C" void kernel_launch(void* const* d_in, const int* in_sizes, int n_in,
                              void* d_out, int out_size) {
    const float* x  = (const float*)d_in[0];
    const int* ei   = (const int*)d_in[1];   // int32 (JAX x64 disabled)
    const float* W1 = (const float*)d_in[2];
    const float* b1 = (const float*)d_in[3];
    const float* W2 = (const float*)d_in[4];
    const float* b2 = (const float*)d_in[5];
    const float* Wfc = (const float*)d_in[6];
    const float* bfc = (const float*)d_in[7];
    float* out = (float*)d_out;

    const int T = 256;
    const int nBlk = (NN + T - 1) / T;
    const int eBlk = (EE + T - 1) / T;

    // --- graph structure (CSR by destination, with edge weights) ---
    k_init<<<nBlk, T>>>();
    k_deg_count<<<eBlk, T>>>(ei);
    k_scan1<<<NB, SCAN_T>>>();
    k_scan2<<<1, 32>>>();
    k_scan3<<<nBlk, T>>>();
    k_bin<<<eBlk, T>>>(ei);

    const int gemmBlocks = (NN + BM - 1) / BM;   // 391
    const int warpBlocks = (NN + 7) / 8;

    // --- conv1 ---
    k_gemm_tc<<<gemmBlocks, 256>>>(x, W1);
    k_gather<<<warpBlocks, T>>>(b1);

    // --- conv2 ---
    k_gemm_tc<<<gemmBlocks, 256>>>(nullptr, W2);
    k_gather<<<warpBlocks, T>>>(b2);

    // --- fc ---
    k_fc<<<warpBlocks, T>>>(Wfc, bfc, out);
}

// round 7
// speedup vs baseline: 1.3389x; 1.0694x over previous
#include <cuda_runtime.h>
#include <cuda_fp16.h>
#include <cstdint>

#define NN 50000
#define EE 600000
#define HID 128
#define NC 21
#define SCAN_T 512
#define NB ((NN + SCAN_T - 1) / SCAN_T)   // 98

// ---------------- scratch (__device__ globals; no cudaMalloc allowed) ------
__device__ __align__(16) __half g_h[NN * HID];    // linear-transform output (fp16)
__device__ __align__(16) float g_agg[NN * HID];   // conv output (post bias+relu)
__device__ float g_dinv[NN];
__device__ int   g_cnt[NN];      // in-degree (without self loop)
__device__ int   g_cur[NN];      // binning cursor
__device__ int   g_rowinc[NN];   // inclusive block-scan
__device__ int   g_row[NN];      // CSR row start (exclusive scan)
__device__ int   g_bsum[NB];     // per-block scan totals
__device__ __align__(8) uint2 g_edge[EE];  // (src, weight-bits) per CSR slot

// ---------------- init: zero degree counters ----------------
__global__ void k_init() {
    int i = blockIdx.x * blockDim.x + threadIdx.x;
    if (i < NN) g_cnt[i] = 0;
}

// edge_index is int32 on device (JAX x64 disabled downcasts int64 -> int32)
__global__ void k_deg_count(const int* __restrict__ ei) {
    int e = blockIdx.x * blockDim.x + threadIdx.x;
    if (e < EE) atomicAdd(&g_cnt[ei[EE + e]], 1);
}

// ---------------- scan: block-local inclusive scan + totals ----------------
__global__ void k_scan1() {
    __shared__ int sh[SCAN_T];
    int gid = blockIdx.x * SCAN_T + threadIdx.x;
    int v = (gid < NN) ? g_cnt[gid] : 0;
    sh[threadIdx.x] = v;
    __syncthreads();
#pragma unroll
    for (int off = 1; off < SCAN_T; off <<= 1) {
        int t = (threadIdx.x >= off) ? sh[threadIdx.x - off] : 0;
        __syncthreads();
        sh[threadIdx.x] += t;
        __syncthreads();
    }
    if (gid < NN) g_rowinc[gid] = sh[threadIdx.x];
    if (threadIdx.x == SCAN_T - 1) g_bsum[blockIdx.x] = sh[threadIdx.x];
}

// scan3: per-block prefix over g_bsum (chunk uniform since 512 = 2*256),
// fused with dinv + cursor zeroing. Replaces the separate scan2 launch.
__global__ void k_scan3() {
    __shared__ int sprefix;
    int chunk = (blockIdx.x * blockDim.x) / SCAN_T;  // uniform for the block
    if (threadIdx.x < 32) {
        int acc = 0;
        for (int base = 0; base < NB; base += 32) {
            int j = base + threadIdx.x;
            acc += (j < chunk) ? g_bsum[j] : 0;
        }
#pragma unroll
        for (int off = 16; off; off >>= 1)
            acc += __shfl_xor_sync(0xffffffffu, acc, off);
        if (threadIdx.x == 0) sprefix = acc;
    }
    __syncthreads();
    int gid = blockIdx.x * blockDim.x + threadIdx.x;
    if (gid < NN) {
        int c = g_cnt[gid];
        g_row[gid] = g_rowinc[gid] - c + sprefix;
        g_dinv[gid] = rsqrtf((float)(c + 1));
        g_cur[gid] = 0;
    }
}

// ---------------- bin edges into interleaved CSR slots ----------------
__global__ void k_bin(const int* __restrict__ ei) {
    int e = blockIdx.x * blockDim.x + threadIdx.x;
    if (e >= EE) return;
    int s = ei[e];
    int d = ei[EE + e];
    int pos = g_row[d] + atomicAdd(&g_cur[d], 1);
    g_edge[pos] = make_uint2((unsigned)s, __float_as_uint(g_dinv[s] * g_dinv[d]));
}

// ---------------- tensor-core GEMM (3xTF32, pre-split smem) ----------------
#define BM 128
#define KC 16
#define SWS 136
#define SAS 20

__device__ __forceinline__ void tf32_split(float v, uint32_t& hi, uint32_t& lo) {
    asm("cvt.rna.tf32.f32 %0, %1;" : "=r"(hi) : "f"(v));
    float r = v - __uint_as_float(hi);
    asm("cvt.rna.tf32.f32 %0, %1;" : "=r"(lo) : "f"(r));
}

__device__ __forceinline__ void mma_tf32(float* d, const uint32_t* a, const uint32_t* b) {
    asm volatile(
        "mma.sync.aligned.m16n8k8.row.col.f32.tf32.tf32.f32 "
        "{%0,%1,%2,%3}, {%4,%5,%6,%7}, {%8,%9}, {%0,%1,%2,%3};"
        : "+f"(d[0]), "+f"(d[1]), "+f"(d[2]), "+f"(d[3])
        : "r"(a[0]), "r"(a[1]), "r"(a[2]), "r"(a[3]), "r"(b[0]), "r"(b[1]));
}

__global__ __launch_bounds__(256) void k_gemm_tc(const float* __restrict__ A,
                                                 const float* __restrict__ W) {
    const float* Ap = A ? A : g_agg;
    __shared__ uint32_t sWh[KC * SWS], sWl[KC * SWS];
    __shared__ uint32_t sAh[BM * SAS], sAl[BM * SAS];

    const int tid  = threadIdx.x;
    const int lane = tid & 31;
    const int warp = tid >> 5;
    const int wm = warp >> 1;
    const int wn = warp & 1;
    const int gid = lane >> 2;
    const int tig = lane & 3;
    const int rowBase = blockIdx.x * BM;

    float acc[2][8][4];
#pragma unroll
    for (int mt = 0; mt < 2; mt++)
#pragma unroll
        for (int nt = 0; nt < 8; nt++)
#pragma unroll
            for (int q = 0; q < 4; q++) acc[mt][nt][q] = 0.f;

    for (int kc = 0; kc < HID; kc += KC) {
        __syncthreads();
#pragma unroll
        for (int i = 0; i < 2; i++) {
            int idx = i * 256 + tid;
            int r = idx >> 5, cq = idx & 31;
            float4 v = *reinterpret_cast<const float4*>(W + (kc + r) * HID + cq * 4);
            uint4 hi, lo;
            tf32_split(v.x, hi.x, lo.x); tf32_split(v.y, hi.y, lo.y);
            tf32_split(v.z, hi.z, lo.z); tf32_split(v.w, hi.w, lo.w);
            *reinterpret_cast<uint4*>(sWh + r * SWS + cq * 4) = hi;
            *reinterpret_cast<uint4*>(sWl + r * SWS + cq * 4) = lo;
        }
#pragma unroll
        for (int i = 0; i < 2; i++) {
            int idx = i * 256 + tid;
            int r = idx >> 2, kq = idx & 3;
            int grow = rowBase + r;
            float4 v = (grow < NN)
                ? *reinterpret_cast<const float4*>(Ap + grow * HID + kc + kq * 4)
                : make_float4(0.f, 0.f, 0.f, 0.f);
            uint4 hi, lo;
            tf32_split(v.x, hi.x, lo.x); tf32_split(v.y, hi.y, lo.y);
            tf32_split(v.z, hi.z, lo.z); tf32_split(v.w, hi.w, lo.w);
            *reinterpret_cast<uint4*>(sAh + r * SAS + kq * 4) = hi;
            *reinterpret_cast<uint4*>(sAl + r * SAS + kq * 4) = lo;
        }
        __syncthreads();

#pragma unroll
        for (int ks = 0; ks < KC; ks += 8) {
            uint32_t ah[2][4], al[2][4];
#pragma unroll
            for (int mt = 0; mt < 2; mt++) {
                int r0 = wm * 32 + mt * 16;
#pragma unroll
                for (int q = 0; q < 4; q++) {
                    int rr = r0 + gid + (q & 1) * 8;
                    int kk = ks + tig + (q >> 1) * 4;
                    ah[mt][q] = sAh[rr * SAS + kk];
                    al[mt][q] = sAl[rr * SAS + kk];
                }
            }
#pragma unroll
            for (int nt = 0; nt < 8; nt++) {
                int c0 = wn * 64 + nt * 8 + gid;
                uint32_t bh[2], bl[2];
#pragma unroll
                for (int q = 0; q < 2; q++) {
                    int kk = ks + tig + q * 4;
                    bh[q] = sWh[kk * SWS + c0];
                    bl[q] = sWl[kk * SWS + c0];
                }
#pragma unroll
                for (int mt = 0; mt < 2; mt++) {
                    mma_tf32(acc[mt][nt], ah[mt], bh);
                    mma_tf32(acc[mt][nt], al[mt], bh);
                    mma_tf32(acc[mt][nt], ah[mt], bl);
                }
            }
        }
    }

    __half2* h2 = reinterpret_cast<__half2*>(g_h);
#pragma unroll
    for (int mt = 0; mt < 2; mt++) {
        int r0 = rowBase + wm * 32 + mt * 16 + gid;
#pragma unroll
        for (int half_ = 0; half_ < 2; half_++) {
            int row = r0 + half_ * 8;
            if (row < NN) {
#pragma unroll
                for (int nt = 0; nt < 8; nt++) {
                    int col = wn * 64 + nt * 8 + tig * 2;
                    h2[row * 64 + (col >> 1)] =
                        __floats2half2_rn(acc[mt][nt][half_ * 2], acc[mt][nt][half_ * 2 + 1]);
                }
            }
        }
    }
}

// ---------------- gather-aggregate + self loop + bias + relu ---------------
__global__ void k_gather(const float* __restrict__ b) {
    const int lane = threadIdx.x & 31;
    int node = blockIdx.x * (blockDim.x >> 5) + (threadIdx.x >> 5);
    if (node >= NN) return;

    const uint2* h4 = reinterpret_cast<const uint2*>(g_h);
    float dn = g_dinv[node];
    float dd = dn * dn;

    uint2 u = h4[node * 32 + lane];
    float2 f0 = __half22float2(*reinterpret_cast<__half2*>(&u.x));
    float2 f1 = __half22float2(*reinterpret_cast<__half2*>(&u.y));
    float4 acc = make_float4(f0.x * dd, f0.y * dd, f1.x * dd, f1.y * dd);

    int beg = g_row[node];
    int cnt = g_cnt[node];
    for (int j0 = 0; j0 < cnt; j0 += 32) {
        int n = min(32, cnt - j0);
        int s = 0; float w = 0.f;
        if (lane < n) {
            uint2 ew = g_edge[beg + j0 + lane];
            s = (int)ew.x;
            w = __uint_as_float(ew.y);
        }
        for (int i = 0; i < n; i++) {
            int   si = __shfl_sync(0xffffffffu, s, i);
            float wi = __shfl_sync(0xffffffffu, w, i);
            uint2 uv = h4[si * 32 + lane];
            float2 v0 = __half22float2(*reinterpret_cast<__half2*>(&uv.x));
            float2 v1 = __half22float2(*reinterpret_cast<__half2*>(&uv.y));
            acc.x += v0.x * wi; acc.y += v0.y * wi;
            acc.z += v1.x * wi; acc.w += v1.y * wi;
        }
    }

    float4 bb = reinterpret_cast<const float4*>(b)[lane];
    acc.x = fmaxf(acc.x + bb.x, 0.f);
    acc.y = fmaxf(acc.y + bb.y, 0.f);
    acc.z = fmaxf(acc.z + bb.z, 0.f);
    acc.w = fmaxf(acc.w + bb.w, 0.f);
    reinterpret_cast<float4*>(g_agg)[node * 32 + lane] = acc;
}

// ---------------- final FC: out[N,21] = g_agg @ Wfc + bfc ------------------
__global__ void k_fc(const float* __restrict__ Wfc, const float* __restrict__ bfc,
                     float* __restrict__ out) {
    __shared__ float WsT[NC * HID];
    __shared__ float bs[NC];
    for (int i = threadIdx.x; i < NC * HID; i += blockDim.x) {
        int c = i >> 7;
        int k = i & 127;
        WsT[i] = Wfc[k * NC + c];
    }
    if (threadIdx.x < NC) bs[threadIdx.x] = bfc[threadIdx.x];
    __syncthreads();

    int lane = threadIdx.x & 31;
    int row = blockIdx.x * (blockDim.x >> 5) + (threadIdx.x >> 5);
    if (row >= NN) return;
    float4 a = reinterpret_cast<const float4*>(g_agg)[row * 32 + lane];
#pragma unroll
    for (int c = 0; c < NC; c++) {
        const float4 w = reinterpret_cast<const float4*>(WsT + c * HID)[lane];
        float p = a.x * w.x + a.y * w.y + a.z * w.z + a.w * w.w;
        p += __shfl_xor_sync(0xffffffffu, p, 16);
        p += __shfl_xor_sync(0xffffffffu, p, 8);
        p += __shfl_xor_sync(0xffffffffu, p, 4);
        p += __shfl_xor_sync(0xffffffffu, p, 2);
        p += __shfl_xor_sync(0xffffffffu, p, 1);
        if (lane == 0) out[row * NC + c] = p + bs[c];
    }
}

// ---------------- launch ----------------
extern "C" void kernel_launch(void* const* d_in, const int* in_sizes, int n_in,
                              void* d_out, int out_size) {
    const float* x  = (const float*)d_in[0];
    const int* ei   = (const int*)d_in[1];   // int32 (JAX x64 disabled)
    const float* W1 = (const float*)d_in[2];
    const float* b1 = (const float*)d_in[3];
    const float* W2 = (const float*)d_in[4];
    const float* b2 = (const float*)d_in[5];
    const float* Wfc = (const float*)d_in[6];
    const float* bfc = (const float*)d_in[7];
    float* out = (float*)d_out;

    // side stream + events, created once and persisted (destroying a stream
    // that participated in capture would invalidate the capture)
    static cudaStream_t s2 = nullptr;
    static cudaEvent_t evFork = nullptr, evJoin = nullptr;
    if (!s2) {
        cudaStreamCreate(&s2);
        cudaEventCreateWithFlags(&evFork, cudaEventDisableTiming);
        cudaEventCreateWithFlags(&evJoin, cudaEventDisableTiming);
    }

    const int T = 256;
    const int nBlk = (NN + T - 1) / T;
    const int eBlk = (EE + T - 1) / T;
    const int gemmBlocks = (NN + BM - 1) / BM;   // 391
    const int warpBlocks = (NN + 7) / 8;

    // fork: GEMM1 (independent of graph structure) on side stream
    cudaEventRecord(evFork, 0);
    cudaStreamWaitEvent(s2, evFork, 0);
    k_gemm_tc<<<gemmBlocks, 256, 0, s2>>>(x, W1);

    // CSR build chain on main stream (concurrent with GEMM1)
    k_init<<<nBlk, T>>>();
    k_deg_count<<<eBlk, T>>>(ei);
    k_scan1<<<NB, SCAN_T>>>();
    k_scan3<<<nBlk, T>>>();
    k_bin<<<eBlk, T>>>(ei);

    // join
    cudaEventRecord(evJoin, s2);
    cudaStreamWaitEvent(0, evJoin, 0);

    // conv1 aggregate, conv2, fc (serial dependencies)
    k_gather<<<warpBlocks, T>>>(b1);
    k_gemm_tc<<<gemmBlocks, 256>>>(nullptr, W2);
    k_gather<<<warpBlocks, T>>>(b2);
    k_fc<<<warpBlocks, T>>>(Wfc, bfc, out);
}

// round 8
// speedup vs baseline: 1.3844x; 1.0340x over previous
#include <cuda_runtime.h>
#include <cuda_fp16.h>
#include <cstdint>

#define NN 50000
#define EE 600000
#define HID 128
#define NC 21
#define SCAN_T 512
#define NB ((NN + SCAN_T - 1) / SCAN_T)   // 98

// ---------------- scratch (__device__ globals; no cudaMalloc allowed) ------
__device__ __align__(16) __half g_h[NN * HID];    // linear-transform output (fp16)
__device__ __align__(16) float g_agg[NN * HID];   // conv1 output (post bias+relu)
__device__ float g_dinv[NN];
__device__ int   g_cnt[NN];
__device__ int   g_cur[NN];
__device__ int   g_rowinc[NN];
__device__ int   g_row[NN];
__device__ int   g_bsum[NB];
__device__ __align__(8) uint2 g_edge[EE];  // (src, weight-bits) per CSR slot

// ---------------- init: zero degree counters ----------------
__global__ void k_init() {
    int i = blockIdx.x * blockDim.x + threadIdx.x;
    if (i < NN) g_cnt[i] = 0;
}

// ---------------- degree count: 4 edges per thread (int4) ----------------
__global__ void k_deg_count(const int* __restrict__ ei) {
    int t = blockIdx.x * blockDim.x + threadIdx.x;
    if (t * 4 >= EE) return;
    int4 d = *reinterpret_cast<const int4*>(ei + EE + t * 4);
    atomicAdd(&g_cnt[d.x], 1);
    atomicAdd(&g_cnt[d.y], 1);
    atomicAdd(&g_cnt[d.z], 1);
    atomicAdd(&g_cnt[d.w], 1);
}

// ---------------- scan1: warp-shuffle block scan ----------------
__global__ void k_scan1() {
    __shared__ int wsum[16];
    int lane = threadIdx.x & 31;
    int wid = threadIdx.x >> 5;
    int gid = blockIdx.x * SCAN_T + threadIdx.x;
    int v = (gid < NN) ? g_cnt[gid] : 0;
    int incl = v;
#pragma unroll
    for (int off = 1; off < 32; off <<= 1) {
        int t = __shfl_up_sync(0xffffffffu, incl, off);
        if (lane >= off) incl += t;
    }
    if (lane == 31) wsum[wid] = incl;
    __syncthreads();
    if (wid == 0) {
        int s = (lane < 16) ? wsum[lane] : 0;
#pragma unroll
        for (int off = 1; off < 16; off <<= 1) {
            int t = __shfl_up_sync(0xffffffffu, s, off);
            if (lane >= off) s += t;
        }
        if (lane < 16) wsum[lane] = s;
    }
    __syncthreads();
    int prefix = (wid > 0) ? wsum[wid - 1] : 0;
    if (gid < NN) g_rowinc[gid] = incl + prefix;
    if (threadIdx.x == SCAN_T - 1) g_bsum[blockIdx.x] = incl + prefix;
}

// scan3: per-block prefix over g_bsum (chunk uniform since 512 = 2*256),
// fused with dinv + cursor zeroing.
__global__ void k_scan3() {
    __shared__ int sprefix;
    int chunk = (blockIdx.x * blockDim.x) / SCAN_T;
    if (threadIdx.x < 32) {
        int acc = 0;
        for (int base = 0; base < NB; base += 32) {
            int j = base + threadIdx.x;
            acc += (j < chunk) ? g_bsum[j] : 0;
        }
#pragma unroll
        for (int off = 16; off; off >>= 1)
            acc += __shfl_xor_sync(0xffffffffu, acc, off);
        if (threadIdx.x == 0) sprefix = acc;
    }
    __syncthreads();
    int gid = blockIdx.x * blockDim.x + threadIdx.x;
    if (gid < NN) {
        int c = g_cnt[gid];
        g_row[gid] = g_rowinc[gid] - c + sprefix;
        g_dinv[gid] = rsqrtf((float)(c + 1));
        g_cur[gid] = 0;
    }
}

// ---------------- bin edges: 4 edges per thread ----------------
__global__ void k_bin(const int* __restrict__ ei) {
    int t = blockIdx.x * blockDim.x + threadIdx.x;
    if (t * 4 >= EE) return;
    int4 sv = *reinterpret_cast<const int4*>(ei + t * 4);
    int4 dv = *reinterpret_cast<const int4*>(ei + EE + t * 4);
#pragma unroll
    for (int q = 0; q < 4; q++) {
        int s = (&sv.x)[q];
        int d = (&dv.x)[q];
        int pos = g_row[d] + atomicAdd(&g_cur[d], 1);
        g_edge[pos] = make_uint2((unsigned)s, __float_as_uint(g_dinv[s] * g_dinv[d]));
    }
}

// ---------------- tensor-core GEMM (3xTF32, pre-split smem) ----------------
#define BM 128
#define KC 16
#define SWS 136
#define SAS 20

__device__ __forceinline__ void tf32_split(float v, uint32_t& hi, uint32_t& lo) {
    asm("cvt.rna.tf32.f32 %0, %1;" : "=r"(hi) : "f"(v));
    float r = v - __uint_as_float(hi);
    asm("cvt.rna.tf32.f32 %0, %1;" : "=r"(lo) : "f"(r));
}

__device__ __forceinline__ void mma_tf32(float* d, const uint32_t* a, const uint32_t* b) {
    asm volatile(
        "mma.sync.aligned.m16n8k8.row.col.f32.tf32.tf32.f32 "
        "{%0,%1,%2,%3}, {%4,%5,%6,%7}, {%8,%9}, {%0,%1,%2,%3};"
        : "+f"(d[0]), "+f"(d[1]), "+f"(d[2]), "+f"(d[3])
        : "r"(a[0]), "r"(a[1]), "r"(a[2]), "r"(a[3]), "r"(b[0]), "r"(b[1]));
}

__global__ __launch_bounds__(256) void k_gemm_tc(const float* __restrict__ A,
                                                 const float* __restrict__ W) {
    const float* Ap = A ? A : g_agg;
    __shared__ uint32_t sWh[KC * SWS], sWl[KC * SWS];
    __shared__ uint32_t sAh[BM * SAS], sAl[BM * SAS];

    const int tid  = threadIdx.x;
    const int lane = tid & 31;
    const int warp = tid >> 5;
    const int wm = warp >> 1;
    const int wn = warp & 1;
    const int gid = lane >> 2;
    const int tig = lane & 3;
    const int rowBase = blockIdx.x * BM;

    float acc[2][8][4];
#pragma unroll
    for (int mt = 0; mt < 2; mt++)
#pragma unroll
        for (int nt = 0; nt < 8; nt++)
#pragma unroll
            for (int q = 0; q < 4; q++) acc[mt][nt][q] = 0.f;

    for (int kc = 0; kc < HID; kc += KC) {
        __syncthreads();
#pragma unroll
        for (int i = 0; i < 2; i++) {
            int idx = i * 256 + tid;
            int r = idx >> 5, cq = idx & 31;
            float4 v = *reinterpret_cast<const float4*>(W + (kc + r) * HID + cq * 4);
            uint4 hi, lo;
            tf32_split(v.x, hi.x, lo.x); tf32_split(v.y, hi.y, lo.y);
            tf32_split(v.z, hi.z, lo.z); tf32_split(v.w, hi.w, lo.w);
            *reinterpret_cast<uint4*>(sWh + r * SWS + cq * 4) = hi;
            *reinterpret_cast<uint4*>(sWl + r * SWS + cq * 4) = lo;
        }
#pragma unroll
        for (int i = 0; i < 2; i++) {
            int idx = i * 256 + tid;
            int r = idx >> 2, kq = idx & 3;
            int grow = rowBase + r;
            float4 v = (grow < NN)
                ? *reinterpret_cast<const float4*>(Ap + grow * HID + kc + kq * 4)
                : make_float4(0.f, 0.f, 0.f, 0.f);
            uint4 hi, lo;
            tf32_split(v.x, hi.x, lo.x); tf32_split(v.y, hi.y, lo.y);
            tf32_split(v.z, hi.z, lo.z); tf32_split(v.w, hi.w, lo.w);
            *reinterpret_cast<uint4*>(sAh + r * SAS + kq * 4) = hi;
            *reinterpret_cast<uint4*>(sAl + r * SAS + kq * 4) = lo;
        }
        __syncthreads();

#pragma unroll
        for (int ks = 0; ks < KC; ks += 8) {
            uint32_t ah[2][4], al[2][4];
#pragma unroll
            for (int mt = 0; mt < 2; mt++) {
                int r0 = wm * 32 + mt * 16;
#pragma unroll
                for (int q = 0; q < 4; q++) {
                    int rr = r0 + gid + (q & 1) * 8;
                    int kk = ks + tig + (q >> 1) * 4;
                    ah[mt][q] = sAh[rr * SAS + kk];
                    al[mt][q] = sAl[rr * SAS + kk];
                }
            }
#pragma unroll
            for (int nt = 0; nt < 8; nt++) {
                int c0 = wn * 64 + nt * 8 + gid;
                uint32_t bh[2], bl[2];
#pragma unroll
                for (int q = 0; q < 2; q++) {
                    int kk = ks + tig + q * 4;
                    bh[q] = sWh[kk * SWS + c0];
                    bl[q] = sWl[kk * SWS + c0];
                }
#pragma unroll
                for (int mt = 0; mt < 2; mt++) {
                    mma_tf32(acc[mt][nt], ah[mt], bh);
                    mma_tf32(acc[mt][nt], al[mt], bh);
                    mma_tf32(acc[mt][nt], ah[mt], bl);
                }
            }
        }
    }

    __half2* h2 = reinterpret_cast<__half2*>(g_h);
#pragma unroll
    for (int mt = 0; mt < 2; mt++) {
        int r0 = rowBase + wm * 32 + mt * 16 + gid;
#pragma unroll
        for (int half_ = 0; half_ < 2; half_++) {
            int row = r0 + half_ * 8;
            if (row < NN) {
#pragma unroll
                for (int nt = 0; nt < 8; nt++) {
                    int col = wn * 64 + nt * 8 + tig * 2;
                    h2[row * 64 + (col >> 1)] =
                        __floats2half2_rn(acc[mt][nt][half_ * 2], acc[mt][nt][half_ * 2 + 1]);
                }
            }
        }
    }
}

// ---------------- gather core: returns post-bias+relu float4 ---------------
__device__ __forceinline__ float4 gather_node(int node, int lane,
                                              const float* __restrict__ b) {
    const uint2* h4 = reinterpret_cast<const uint2*>(g_h);
    float dn = g_dinv[node];
    float dd = dn * dn;

    uint2 u = h4[node * 32 + lane];
    float2 f0 = __half22float2(*reinterpret_cast<__half2*>(&u.x));
    float2 f1 = __half22float2(*reinterpret_cast<__half2*>(&u.y));
    float4 acc = make_float4(f0.x * dd, f0.y * dd, f1.x * dd, f1.y * dd);

    int beg = g_row[node];
    int cnt = g_cnt[node];
    for (int j0 = 0; j0 < cnt; j0 += 32) {
        int n = min(32, cnt - j0);
        int s = 0; float w = 0.f;
        if (lane < n) {
            uint2 ew = g_edge[beg + j0 + lane];
            s = (int)ew.x;
            w = __uint_as_float(ew.y);
        }
        for (int i = 0; i < n; i++) {
            int   si = __shfl_sync(0xffffffffu, s, i);
            float wi = __shfl_sync(0xffffffffu, w, i);
            uint2 uv = h4[si * 32 + lane];
            float2 v0 = __half22float2(*reinterpret_cast<__half2*>(&uv.x));
            float2 v1 = __half22float2(*reinterpret_cast<__half2*>(&uv.y));
            acc.x += v0.x * wi; acc.y += v0.y * wi;
            acc.z += v1.x * wi; acc.w += v1.y * wi;
        }
    }

    float4 bb = reinterpret_cast<const float4*>(b)[lane];
    acc.x = fmaxf(acc.x + bb.x, 0.f);
    acc.y = fmaxf(acc.y + bb.y, 0.f);
    acc.z = fmaxf(acc.z + bb.z, 0.f);
    acc.w = fmaxf(acc.w + bb.w, 0.f);
    return acc;
}

// ---------------- gather1: writes g_agg ----------------
__global__ void k_gather(const float* __restrict__ b) {
    const int lane = threadIdx.x & 31;
    int node = blockIdx.x * (blockDim.x >> 5) + (threadIdx.x >> 5);
    if (node >= NN) return;
    float4 acc = gather_node(node, lane, b);
    reinterpret_cast<float4*>(g_agg)[node * 32 + lane] = acc;
}

// ---------------- gather2 + FC fused: writes logits directly ----------------
__global__ void k_gather_fc(const float* __restrict__ b,
                            const float* __restrict__ Wfc,
                            const float* __restrict__ bfc,
                            float* __restrict__ out) {
    __shared__ float WsT[NC * HID];  // [c][k]
    __shared__ float bs[NC];
    for (int i = threadIdx.x; i < NC * HID; i += blockDim.x) {
        int c = i >> 7;
        int k = i & 127;
        WsT[i] = Wfc[k * NC + c];
    }
    if (threadIdx.x < NC) bs[threadIdx.x] = bfc[threadIdx.x];
    __syncthreads();

    const int lane = threadIdx.x & 31;
    int node = blockIdx.x * (blockDim.x >> 5) + (threadIdx.x >> 5);
    if (node >= NN) return;
    float4 a = gather_node(node, lane, b);

#pragma unroll
    for (int c = 0; c < NC; c++) {
        const float4 w = reinterpret_cast<const float4*>(WsT + c * HID)[lane];
        float p = a.x * w.x + a.y * w.y + a.z * w.z + a.w * w.w;
        p += __shfl_xor_sync(0xffffffffu, p, 16);
        p += __shfl_xor_sync(0xffffffffu, p, 8);
        p += __shfl_xor_sync(0xffffffffu, p, 4);
        p += __shfl_xor_sync(0xffffffffu, p, 2);
        p += __shfl_xor_sync(0xffffffffu, p, 1);
        if (lane == 0) out[node * NC + c] = p + bs[c];
    }
}

// ---------------- launch ----------------
extern "C" void kernel_launch(void* const* d_in, const int* in_sizes, int n_in,
                              void* d_out, int out_size) {
    const float* x  = (const float*)d_in[0];
    const int* ei   = (const int*)d_in[1];   // int32 (JAX x64 disabled)
    const float* W1 = (const float*)d_in[2];
    const float* b1 = (const float*)d_in[3];
    const float* W2 = (const float*)d_in[4];
    const float* b2 = (const float*)d_in[5];
    const float* Wfc = (const float*)d_in[6];
    const float* bfc = (const float*)d_in[7];
    float* out = (float*)d_out;

    static cudaStream_t s2 = nullptr;
    static cudaEvent_t evFork = nullptr, evJoin = nullptr;
    if (!s2) {
        cudaStreamCreate(&s2);
        cudaEventCreateWithFlags(&evFork, cudaEventDisableTiming);
        cudaEventCreateWithFlags(&evJoin, cudaEventDisableTiming);
    }

    const int T = 256;
    const int nBlk = (NN + T - 1) / T;
    const int eBlk4 = (EE / 4 + T - 1) / T;
    const int gemmBlocks = (NN + BM - 1) / BM;   // 391
    const int warpBlocks = (NN + 7) / 8;

    // fork: GEMM1 (independent of graph structure) on side stream
    cudaEventRecord(evFork, 0);
    cudaStreamWaitEvent(s2, evFork, 0);
    k_gemm_tc<<<gemmBlocks, 256, 0, s2>>>(x, W1);

    // CSR build chain on main stream (concurrent with GEMM1)
    k_init<<<nBlk, T>>>();
    k_deg_count<<<eBlk4, T>>>(ei);
    k_scan1<<<NB, SCAN_T>>>();
    k_scan3<<<nBlk, T>>>();
    k_bin<<<eBlk4, T>>>(ei);

    // join
    cudaEventRecord(evJoin, s2);
    cudaStreamWaitEvent(0, evJoin, 0);

    // conv1 aggregate -> GEMM2 -> fused conv2-aggregate+FC
    k_gather<<<warpBlocks, T>>>(b1);
    k_gemm_tc<<<gemmBlocks, 256>>>(nullptr, W2);
    k_gather_fc<<<warpBlocks, T>>>(b2, Wfc, bfc, out);
}

// round 10
// speedup vs baseline: 1.6412x; 1.1855x over previous
#include <cuda_runtime.h>
#include <cuda_fp16.h>
#include <cstdint>

#define NN 50000
#define EE 600000
#define HID 128
#define NC 21
#define SCAN_T 512
#define NB ((NN + SCAN_T - 1) / SCAN_T)   // 98

// ---------------- scratch (__device__ globals; no cudaMalloc allowed) ------
__device__ __align__(16) __half g_h[NN * HID];    // linear-transform output (fp16)
__device__ __align__(16) float g_agg[NN * HID];   // conv1 output (post bias+relu)
__device__ float g_dinv[NN];
__device__ int   g_cnt[NN];
__device__ int   g_cur[NN];
__device__ int   g_rowinc[NN];
__device__ int   g_row[NN];
__device__ int   g_bsum[NB];
__device__ __align__(8) uint2 g_edge[EE];  // (src, weight-bits) per CSR slot

// ---------------- init: zero degree counters ----------------
__global__ void k_init() {
    int i = blockIdx.x * blockDim.x + threadIdx.x;
    if (i < NN) g_cnt[i] = 0;
}

// ---------------- degree count: 4 edges per thread (int4) ----------------
__global__ void k_deg_count(const int* __restrict__ ei) {
    int t = blockIdx.x * blockDim.x + threadIdx.x;
    if (t * 4 >= EE) return;
    int4 d = *reinterpret_cast<const int4*>(ei + EE + t * 4);
    atomicAdd(&g_cnt[d.x], 1);
    atomicAdd(&g_cnt[d.y], 1);
    atomicAdd(&g_cnt[d.z], 1);
    atomicAdd(&g_cnt[d.w], 1);
}

// ---------------- scan1: warp-shuffle block scan ----------------
__global__ void k_scan1() {
    __shared__ int wsum[16];
    int lane = threadIdx.x & 31;
    int wid = threadIdx.x >> 5;
    int gid = blockIdx.x * SCAN_T + threadIdx.x;
    int v = (gid < NN) ? g_cnt[gid] : 0;
    int incl = v;
#pragma unroll
    for (int off = 1; off < 32; off <<= 1) {
        int t = __shfl_up_sync(0xffffffffu, incl, off);
        if (lane >= off) incl += t;
    }
    if (lane == 31) wsum[wid] = incl;
    __syncthreads();
    if (wid == 0) {
        int s = (lane < 16) ? wsum[lane] : 0;
#pragma unroll
        for (int off = 1; off < 16; off <<= 1) {
            int t = __shfl_up_sync(0xffffffffu, s, off);
            if (lane >= off) s += t;
        }
        if (lane < 16) wsum[lane] = s;
    }
    __syncthreads();
    int prefix = (wid > 0) ? wsum[wid - 1] : 0;
    if (gid < NN) g_rowinc[gid] = incl + prefix;
    if (threadIdx.x == SCAN_T - 1) g_bsum[blockIdx.x] = incl + prefix;
}

// scan3: per-block prefix over g_bsum, fused with dinv + cursor zeroing
__global__ void k_scan3() {
    __shared__ int sprefix;
    int chunk = (blockIdx.x * blockDim.x) / SCAN_T;
    if (threadIdx.x < 32) {
        int acc = 0;
        for (int base = 0; base < NB; base += 32) {
            int j = base + threadIdx.x;
            acc += (j < chunk) ? g_bsum[j] : 0;
        }
#pragma unroll
        for (int off = 16; off; off >>= 1)
            acc += __shfl_xor_sync(0xffffffffu, acc, off);
        if (threadIdx.x == 0) sprefix = acc;
    }
    __syncthreads();
    int gid = blockIdx.x * blockDim.x + threadIdx.x;
    if (gid < NN) {
        int c = g_cnt[gid];
        g_row[gid] = g_rowinc[gid] - c + sprefix;
        g_dinv[gid] = rsqrtf((float)(c + 1));
        g_cur[gid] = 0;
    }
}

// ---------------- bin edges: 4 edges per thread ----------------
__global__ void k_bin(const int* __restrict__ ei) {
    int t = blockIdx.x * blockDim.x + threadIdx.x;
    if (t * 4 >= EE) return;
    int4 sv = *reinterpret_cast<const int4*>(ei + t * 4);
    int4 dv = *reinterpret_cast<const int4*>(ei + EE + t * 4);
#pragma unroll
    for (int q = 0; q < 4; q++) {
        int s = (&sv.x)[q];
        int d = (&dv.x)[q];
        int pos = g_row[d] + atomicAdd(&g_cur[d], 1);
        g_edge[pos] = make_uint2((unsigned)s, __float_as_uint(g_dinv[s] * g_dinv[d]));
    }
}

// ---------------- fp16 tensor-core GEMM: g_h = fp16(A) @ fp16(W) -----------
// block 128x128, 8 warps each 32x64; mma.m16n8k16.f32.f16.f16.f32
// A staged fp16 [128][72] (stride pad), W staged fp16 row-major [64][136]
#define BM 128
#define KC2 64
#define SAH 72    // halves per A row  (64 + 8)   -> frag reads conflict-free
#define SWN 136   // halves per W row  (128 + 8)  -> frag reads conflict-free

__device__ __forceinline__ uint32_t h2_pack(float a, float b) {
    __half2 h = __floats2half2_rn(a, b);
    return *reinterpret_cast<uint32_t*>(&h);
}

__device__ __forceinline__ void mma_fp16(float* d, const uint32_t* a, const uint32_t* b) {
    asm volatile(
        "mma.sync.aligned.m16n8k16.row.col.f32.f16.f16.f32 "
        "{%0,%1,%2,%3}, {%4,%5,%6,%7}, {%8,%9}, {%0,%1,%2,%3};"
        : "+f"(d[0]), "+f"(d[1]), "+f"(d[2]), "+f"(d[3])
        : "r"(a[0]), "r"(a[1]), "r"(a[2]), "r"(a[3]), "r"(b[0]), "r"(b[1]));
}

__global__ __launch_bounds__(256) void k_gemm_fp16(const float* __restrict__ A,
                                                   const float* __restrict__ W) {
    const float* Ap = A ? A : g_agg;
    __shared__ __half sA[BM * SAH];    // 18432 B
    __shared__ __half sW[KC2 * SWN];   // 17408 B

    const int tid  = threadIdx.x;
    const int lane = tid & 31;
    const int warp = tid >> 5;
    const int wm = warp >> 1;
    const int wn = warp & 1;
    const int gid = lane >> 2;
    const int tig = lane & 3;
    const int rowBase = blockIdx.x * BM;

    float acc[2][8][4];
#pragma unroll
    for (int mt = 0; mt < 2; mt++)
#pragma unroll
        for (int nt = 0; nt < 8; nt++)
#pragma unroll
            for (int q = 0; q < 4; q++) acc[mt][nt][q] = 0.f;

    for (int kc = 0; kc < HID; kc += KC2) {
        __syncthreads();
        // W chunk [64][128] fp32 -> fp16 row-major; 2048 float4, 8/thread
#pragma unroll
        for (int i = 0; i < 8; i++) {
            int idx = i * 256 + tid;
            int r = idx >> 5, cq = idx & 31;
            float4 v = *reinterpret_cast<const float4*>(W + (kc + r) * HID + cq * 4);
            *reinterpret_cast<uint2*>(&sW[r * SWN + cq * 4]) =
                make_uint2(h2_pack(v.x, v.y), h2_pack(v.z, v.w));
        }
        // A chunk [128][64] fp32 -> fp16; 2048 float4, 8/thread
#pragma unroll
        for (int i = 0; i < 8; i++) {
            int idx = i * 256 + tid;
            int r = idx >> 4, kq = idx & 15;
            int grow = rowBase + r;
            float4 v = (grow < NN)
                ? *reinterpret_cast<const float4*>(Ap + grow * HID + kc + kq * 4)
                : make_float4(0.f, 0.f, 0.f, 0.f);
            *reinterpret_cast<uint2*>(&sA[r * SAH + kq * 4]) =
                make_uint2(h2_pack(v.x, v.y), h2_pack(v.z, v.w));
        }
        __syncthreads();

        const unsigned short* sWu = reinterpret_cast<const unsigned short*>(sW);
#pragma unroll
        for (int ks = 0; ks < 4; ks++) {
            int k0 = ks * 16;
            uint32_t a[2][4];
#pragma unroll
            for (int mt = 0; mt < 2; mt++) {
                int r0 = wm * 32 + mt * 16;
                a[mt][0] = *reinterpret_cast<const uint32_t*>(&sA[(r0 + gid) * SAH + k0 + 2 * tig]);
                a[mt][1] = *reinterpret_cast<const uint32_t*>(&sA[(r0 + gid + 8) * SAH + k0 + 2 * tig]);
                a[mt][2] = *reinterpret_cast<const uint32_t*>(&sA[(r0 + gid) * SAH + k0 + 2 * tig + 8]);
                a[mt][3] = *reinterpret_cast<const uint32_t*>(&sA[(r0 + gid + 8) * SAH + k0 + 2 * tig + 8]);
            }
#pragma unroll
            for (int nt = 0; nt < 8; nt++) {
                int c0 = wn * 64 + nt * 8 + gid;
                uint32_t w00 = sWu[(k0 + 2 * tig)     * SWN + c0];
                uint32_t w01 = sWu[(k0 + 2 * tig + 1) * SWN + c0];
                uint32_t w10 = sWu[(k0 + 2 * tig + 8) * SWN + c0];
                uint32_t w11 = sWu[(k0 + 2 * tig + 9) * SWN + c0];
                uint32_t b[2];
                b[0] = w00 | (w01 << 16);
                b[1] = w10 | (w11 << 16);
                mma_fp16(acc[0][nt], a[0], b);
                mma_fp16(acc[1][nt], a[1], b);
            }
        }
    }

    // epilogue -> fp16 h; c0/c1 -> (row, 2*tig), c2/c3 -> (row+8, 2*tig)
    __half2* h2 = reinterpret_cast<__half2*>(g_h);
#pragma unroll
    for (int mt = 0; mt < 2; mt++) {
        int r0 = rowBase + wm * 32 + mt * 16 + gid;
#pragma unroll
        for (int half_ = 0; half_ < 2; half_++) {
            int row = r0 + half_ * 8;
            if (row < NN) {
#pragma unroll
                for (int nt = 0; nt < 8; nt++) {
                    int col = wn * 64 + nt * 8 + tig * 2;
                    h2[row * 64 + (col >> 1)] =
                        __floats2half2_rn(acc[mt][nt][half_ * 2], acc[mt][nt][half_ * 2 + 1]);
                }
            }
        }
    }
}

// ---------------- gather core: returns post-bias+relu float4 ---------------
__device__ __forceinline__ float4 gather_node(int node, int lane,
                                              const float* __restrict__ b) {
    const uint2* h4 = reinterpret_cast<const uint2*>(g_h);
    float dn = g_dinv[node];
    float dd = dn * dn;

    uint2 u = h4[node * 32 + lane];
    float2 f0 = __half22float2(*reinterpret_cast<__half2*>(&u.x));
    float2 f1 = __half22float2(*reinterpret_cast<__half2*>(&u.y));
    float4 acc = make_float4(f0.x * dd, f0.y * dd, f1.x * dd, f1.y * dd);

    int beg = g_row[node];
    int cnt = g_cnt[node];
    for (int j0 = 0; j0 < cnt; j0 += 32) {
        int n = min(32, cnt - j0);
        int s = 0; float w = 0.f;
        if (lane < n) {
            uint2 ew = g_edge[beg + j0 + lane];
            s = (int)ew.x;
            w = __uint_as_float(ew.y);
        }
        for (int i = 0; i < n; i++) {
            int   si = __shfl_sync(0xffffffffu, s, i);
            float wi = __shfl_sync(0xffffffffu, w, i);
            uint2 uv = h4[si * 32 + lane];
            float2 v0 = __half22float2(*reinterpret_cast<__half2*>(&uv.x));
            float2 v1 = __half22float2(*reinterpret_cast<__half2*>(&uv.y));
            acc.x += v0.x * wi; acc.y += v0.y * wi;
            acc.z += v1.x * wi; acc.w += v1.y * wi;
        }
    }

    float4 bb = reinterpret_cast<const float4*>(b)[lane];
    acc.x = fmaxf(acc.x + bb.x, 0.f);
    acc.y = fmaxf(acc.y + bb.y, 0.f);
    acc.z = fmaxf(acc.z + bb.z, 0.f);
    acc.w = fmaxf(acc.w + bb.w, 0.f);
    return acc;
}

// ---------------- gather1: writes g_agg ----------------
__global__ void k_gather(const float* __restrict__ b) {
    const int lane = threadIdx.x & 31;
    int node = blockIdx.x * (blockDim.x >> 5) + (threadIdx.x >> 5);
    if (node >= NN) return;
    float4 acc = gather_node(node, lane, b);
    reinterpret_cast<float4*>(g_agg)[node * 32 + lane] = acc;
}

// ---------------- gather2 + FC fused: writes logits directly ----------------
__global__ void k_gather_fc(const float* __restrict__ b,
                            const float* __restrict__ Wfc,
                            const float* __restrict__ bfc,
                            float* __restrict__ out) {
    __shared__ float WsT[NC * HID];  // [c][k]
    __shared__ float bs[NC];
    for (int i = threadIdx.x; i < NC * HID; i += blockDim.x) {
        int c = i >> 7;
        int k = i & 127;
        WsT[i] = Wfc[k * NC + c];
    }
    if (threadIdx.x < NC) bs[threadIdx.x] = bfc[threadIdx.x];
    __syncthreads();

    const int lane = threadIdx.x & 31;
    int node = blockIdx.x * (blockDim.x >> 5) + (threadIdx.x >> 5);
    if (node >= NN) return;
    float4 a = gather_node(node, lane, b);

#pragma unroll
    for (int c = 0; c < NC; c++) {
        const float4 w = reinterpret_cast<const float4*>(WsT + c * HID)[lane];
        float p = a.x * w.x + a.y * w.y + a.z * w.z + a.w * w.w;
        p += __shfl_xor_sync(0xffffffffu, p, 16);
        p += __shfl_xor_sync(0xffffffffu, p, 8);
        p += __shfl_xor_sync(0xffffffffu, p, 4);
        p += __shfl_xor_sync(0xffffffffu, p, 2);
        p += __shfl_xor_sync(0xffffffffu, p, 1);
        if (lane == 0) out[node * NC + c] = p + bs[c];
    }
}

// ---------------- launch ----------------
extern "C" void kernel_launch(void* const* d_in, const int* in_sizes, int n_in,
                              void* d_out, int out_size) {
    const float* x  = (const float*)d_in[0];
    const int* ei   = (const int*)d_in[1];   // int32 (JAX x64 disabled)
    const float* W1 = (const float*)d_in[2];
    const float* b1 = (const float*)d_in[3];
    const float* W2 = (const float*)d_in[4];
    const float* b2 = (const float*)d_in[5];
    const float* Wfc = (const float*)d_in[6];
    const float* bfc = (const float*)d_in[7];
    float* out = (float*)d_out;

    static cudaStream_t s2 = nullptr;
    static cudaEvent_t evFork = nullptr, evJoin = nullptr;
    if (!s2) {
        cudaStreamCreate(&s2);
        cudaEventCreateWithFlags(&evFork, cudaEventDisableTiming);
        cudaEventCreateWithFlags(&evJoin, cudaEventDisableTiming);
    }

    const int T = 256;
    const int nBlk = (NN + T - 1) / T;
    const int eBlk4 = (EE / 4 + T - 1) / T;
    const int gemmBlocks = (NN + BM - 1) / BM;   // 391
    const int warpBlocks = (NN + 7) / 8;

    // fork: GEMM1 (independent of graph structure) on side stream
    cudaEventRecord(evFork, 0);
    cudaStreamWaitEvent(s2, evFork, 0);
    k_gemm_fp16<<<gemmBlocks, 256, 0, s2>>>(x, W1);

    // CSR build chain on main stream (concurrent with GEMM1)
    k_init<<<nBlk, T>>>();
    k_deg_count<<<eBlk4, T>>>(ei);
    k_scan1<<<NB, SCAN_T>>>();
    k_scan3<<<nBlk, T>>>();
    k_bin<<<eBlk4, T>>>(ei);

    // join
    cudaEventRecord(evJoin, s2);
    cudaStreamWaitEvent(0, evJoin, 0);

    // conv1 aggregate -> GEMM2 -> fused conv2-aggregate+FC
    k_gather<<<warpBlocks, T>>>(b1);
    k_gemm_fp16<<<gemmBlocks, 256>>>(nullptr, W2);
    k_gather_fc<<<warpBlocks, T>>>(b2, Wfc, bfc, out);
}

// round 11
// speedup vs baseline: 1.8302x; 1.1152x over previous
#include <cuda_runtime.h>
#include <cuda_fp16.h>
#include <cstdint>

#define NN 50000
#define EE 600000
#define HID 128
#define NC 21
#define SCAN_T 512
#define NB ((NN + SCAN_T - 1) / SCAN_T)   // 98

// ---------------- scratch (__device__ globals; no cudaMalloc allowed) ------
__device__ __align__(16) __half g_h[NN * HID];    // GEMM output (fp16)
__device__ __align__(16) __half g_a2[NN * HID];   // conv1 output (fp16)
__device__ float g_dinv[NN];
__device__ int   g_cnt[NN];
__device__ int   g_cur[NN];
__device__ int   g_rowinc[NN];
__device__ int   g_row[NN];
__device__ int   g_bsum[NB];
__device__ __align__(8) uint2 g_edge[EE];  // (src, weight-bits) per CSR slot

// ---------------- init: zero degree counters ----------------
__global__ void k_init() {
    int i = blockIdx.x * blockDim.x + threadIdx.x;
    if (i < NN) g_cnt[i] = 0;
}

// ---------------- degree count: 4 edges per thread (int4) ----------------
__global__ void k_deg_count(const int* __restrict__ ei) {
    int t = blockIdx.x * blockDim.x + threadIdx.x;
    if (t * 4 >= EE) return;
    int4 d = *reinterpret_cast<const int4*>(ei + EE + t * 4);
    atomicAdd(&g_cnt[d.x], 1);
    atomicAdd(&g_cnt[d.y], 1);
    atomicAdd(&g_cnt[d.z], 1);
    atomicAdd(&g_cnt[d.w], 1);
}

// ---------------- scan1: warp-shuffle block scan ----------------
__global__ void k_scan1() {
    __shared__ int wsum[16];
    int lane = threadIdx.x & 31;
    int wid = threadIdx.x >> 5;
    int gid = blockIdx.x * SCAN_T + threadIdx.x;
    int v = (gid < NN) ? g_cnt[gid] : 0;
    int incl = v;
#pragma unroll
    for (int off = 1; off < 32; off <<= 1) {
        int t = __shfl_up_sync(0xffffffffu, incl, off);
        if (lane >= off) incl += t;
    }
    if (lane == 31) wsum[wid] = incl;
    __syncthreads();
    if (wid == 0) {
        int s = (lane < 16) ? wsum[lane] : 0;
#pragma unroll
        for (int off = 1; off < 16; off <<= 1) {
            int t = __shfl_up_sync(0xffffffffu, s, off);
            if (lane >= off) s += t;
        }
        if (lane < 16) wsum[lane] = s;
    }
    __syncthreads();
    int prefix = (wid > 0) ? wsum[wid - 1] : 0;
    if (gid < NN) g_rowinc[gid] = incl + prefix;
    if (threadIdx.x == SCAN_T - 1) g_bsum[blockIdx.x] = incl + prefix;
}

// scan3: per-block prefix over g_bsum, fused with dinv + cursor zeroing
__global__ void k_scan3() {
    __shared__ int sprefix;
    int chunk = (blockIdx.x * blockDim.x) / SCAN_T;
    if (threadIdx.x < 32) {
        int acc = 0;
        for (int base = 0; base < NB; base += 32) {
            int j = base + threadIdx.x;
            acc += (j < chunk) ? g_bsum[j] : 0;
        }
#pragma unroll
        for (int off = 16; off; off >>= 1)
            acc += __shfl_xor_sync(0xffffffffu, acc, off);
        if (threadIdx.x == 0) sprefix = acc;
    }
    __syncthreads();
    int gid = blockIdx.x * blockDim.x + threadIdx.x;
    if (gid < NN) {
        int c = g_cnt[gid];
        g_row[gid] = g_rowinc[gid] - c + sprefix;
        g_dinv[gid] = rsqrtf((float)(c + 1));
        g_cur[gid] = 0;
    }
}

// ---------------- bin edges: 4 edges per thread ----------------
__global__ void k_bin(const int* __restrict__ ei) {
    int t = blockIdx.x * blockDim.x + threadIdx.x;
    if (t * 4 >= EE) return;
    int4 sv = *reinterpret_cast<const int4*>(ei + t * 4);
    int4 dv = *reinterpret_cast<const int4*>(ei + EE + t * 4);
#pragma unroll
    for (int q = 0; q < 4; q++) {
        int s = (&sv.x)[q];
        int d = (&dv.x)[q];
        int pos = g_row[d] + atomicAdd(&g_cur[d], 1);
        g_edge[pos] = make_uint2((unsigned)s, __float_as_uint(g_dinv[s] * g_dinv[d]));
    }
}

// ---------------- fp16 tensor-core GEMM: g_h = fp16(A) @ fp16(W) -----------
// block 128x128, 8 warps each 32x64; mma.m16n8k16.f32.f16.f16.f32
// A: fp32 input (converted) or fp16 g_a2 (raw copy). W staged fp16 [64][136].
#define BM 128
#define KC2 64
#define SAH 72    // halves per A row  (64 + 8)
#define SWN 136   // halves per W row  (128 + 8)

__device__ __forceinline__ uint32_t h2_pack(float a, float b) {
    __half2 h = __floats2half2_rn(a, b);
    return *reinterpret_cast<uint32_t*>(&h);
}

__device__ __forceinline__ void mma_fp16(float* d, const uint32_t* a, const uint32_t* b) {
    asm volatile(
        "mma.sync.aligned.m16n8k16.row.col.f32.f16.f16.f32 "
        "{%0,%1,%2,%3}, {%4,%5,%6,%7}, {%8,%9}, {%0,%1,%2,%3};"
        : "+f"(d[0]), "+f"(d[1]), "+f"(d[2]), "+f"(d[3])
        : "r"(a[0]), "r"(a[1]), "r"(a[2]), "r"(a[3]), "r"(b[0]), "r"(b[1]));
}

__global__ __launch_bounds__(256) void k_gemm_fp16(const float* __restrict__ A,
                                                   const float* __restrict__ W) {
    __shared__ __half sA[BM * SAH];    // 18432 B
    __shared__ __half sW[KC2 * SWN];   // 17408 B

    const int tid  = threadIdx.x;
    const int lane = tid & 31;
    const int warp = tid >> 5;
    const int wm = warp >> 1;
    const int wn = warp & 1;
    const int gid = lane >> 2;
    const int tig = lane & 3;
    const int rowBase = blockIdx.x * BM;

    float acc[2][8][4];
#pragma unroll
    for (int mt = 0; mt < 2; mt++)
#pragma unroll
        for (int nt = 0; nt < 8; nt++)
#pragma unroll
            for (int q = 0; q < 4; q++) acc[mt][nt][q] = 0.f;

    for (int kc = 0; kc < HID; kc += KC2) {
        __syncthreads();
        // W chunk [64][128] fp32 -> fp16 row-major; 2048 float4, 8/thread
#pragma unroll
        for (int i = 0; i < 8; i++) {
            int idx = i * 256 + tid;
            int r = idx >> 5, cq = idx & 31;
            float4 v = *reinterpret_cast<const float4*>(W + (kc + r) * HID + cq * 4);
            *reinterpret_cast<uint2*>(&sW[r * SWN + cq * 4]) =
                make_uint2(h2_pack(v.x, v.y), h2_pack(v.z, v.w));
        }
        if (A) {
            // A chunk [128][64] fp32 -> fp16; 2048 float4, 8/thread
#pragma unroll
            for (int i = 0; i < 8; i++) {
                int idx = i * 256 + tid;
                int r = idx >> 4, kq = idx & 15;
                int grow = rowBase + r;
                float4 v = (grow < NN)
                    ? *reinterpret_cast<const float4*>(A + grow * HID + kc + kq * 4)
                    : make_float4(0.f, 0.f, 0.f, 0.f);
                *reinterpret_cast<uint2*>(&sA[r * SAH + kq * 4]) =
                    make_uint2(h2_pack(v.x, v.y), h2_pack(v.z, v.w));
            }
        } else {
            // A chunk [128][64] raw fp16 copy from g_a2; 1024 uint4, 4/thread
#pragma unroll
            for (int i = 0; i < 4; i++) {
                int idx = i * 256 + tid;
                int r = idx >> 3, kq = idx & 7;   // 8 uint4 per row
                int grow = rowBase + r;
                uint4 v = (grow < NN)
                    ? *reinterpret_cast<const uint4*>(g_a2 + grow * HID + kc + kq * 8)
                    : make_uint4(0u, 0u, 0u, 0u);
                *reinterpret_cast<uint4*>(&sA[r * SAH + kq * 8]) = v;
            }
        }
        __syncthreads();

        const unsigned short* sWu = reinterpret_cast<const unsigned short*>(sW);
#pragma unroll
        for (int ks = 0; ks < 4; ks++) {
            int k0 = ks * 16;
            uint32_t a[2][4];
#pragma unroll
            for (int mt = 0; mt < 2; mt++) {
                int r0 = wm * 32 + mt * 16;
                a[mt][0] = *reinterpret_cast<const uint32_t*>(&sA[(r0 + gid) * SAH + k0 + 2 * tig]);
                a[mt][1] = *reinterpret_cast<const uint32_t*>(&sA[(r0 + gid + 8) * SAH + k0 + 2 * tig]);
                a[mt][2] = *reinterpret_cast<const uint32_t*>(&sA[(r0 + gid) * SAH + k0 + 2 * tig + 8]);
                a[mt][3] = *reinterpret_cast<const uint32_t*>(&sA[(r0 + gid + 8) * SAH + k0 + 2 * tig + 8]);
            }
#pragma unroll
            for (int nt = 0; nt < 8; nt++) {
                int c0 = wn * 64 + nt * 8 + gid;
                uint32_t w00 = sWu[(k0 + 2 * tig)     * SWN + c0];
                uint32_t w01 = sWu[(k0 + 2 * tig + 1) * SWN + c0];
                uint32_t w10 = sWu[(k0 + 2 * tig + 8) * SWN + c0];
                uint32_t w11 = sWu[(k0 + 2 * tig + 9) * SWN + c0];
                uint32_t b[2];
                b[0] = w00 | (w01 << 16);
                b[1] = w10 | (w11 << 16);
                mma_fp16(acc[0][nt], a[0], b);
                mma_fp16(acc[1][nt], a[1], b);
            }
        }
    }

    // epilogue -> fp16 h
    __half2* h2 = reinterpret_cast<__half2*>(g_h);
#pragma unroll
    for (int mt = 0; mt < 2; mt++) {
        int r0 = rowBase + wm * 32 + mt * 16 + gid;
#pragma unroll
        for (int half_ = 0; half_ < 2; half_++) {
            int row = r0 + half_ * 8;
            if (row < NN) {
#pragma unroll
                for (int nt = 0; nt < 8; nt++) {
                    int col = wn * 64 + nt * 8 + tig * 2;
                    h2[row * 64 + (col >> 1)] =
                        __floats2half2_rn(acc[mt][nt][half_ * 2], acc[mt][nt][half_ * 2 + 1]);
                }
            }
        }
    }
}

// ---------------- gather core: 4-way unrolled edge loop --------------------
// lanes >= n carry s=0/w=0, so over-read iterations are multiplies by zero
__device__ __forceinline__ float4 gather_node(int node, int lane,
                                              const float* __restrict__ b) {
    const uint2* h4 = reinterpret_cast<const uint2*>(g_h);
    float dn = g_dinv[node];
    float dd = dn * dn;

    uint2 u = h4[node * 32 + lane];
    float2 f0 = __half22float2(*reinterpret_cast<__half2*>(&u.x));
    float2 f1 = __half22float2(*reinterpret_cast<__half2*>(&u.y));
    float4 acc = make_float4(f0.x * dd, f0.y * dd, f1.x * dd, f1.y * dd);

    int beg = g_row[node];
    int cnt = g_cnt[node];
    for (int j0 = 0; j0 < cnt; j0 += 32) {
        int n = min(32, cnt - j0);
        int s = 0; float w = 0.f;
        if (lane < n) {
            uint2 ew = g_edge[beg + j0 + lane];
            s = (int)ew.x;
            w = __uint_as_float(ew.y);
        }
        for (int i = 0; i < n; i += 4) {
            // issue 4 independent row loads (weight-zero padded past n)
            uint2 uv[4]; float wv[4];
#pragma unroll
            for (int j = 0; j < 4; j++) {
                int   si = __shfl_sync(0xffffffffu, s, (i + j) & 31);
                wv[j] = __shfl_sync(0xffffffffu, w, (i + j) & 31);
                if (i + j >= n) wv[j] = 0.f;
                uv[j] = h4[si * 32 + lane];
            }
#pragma unroll
            for (int j = 0; j < 4; j++) {
                float2 v0 = __half22float2(*reinterpret_cast<__half2*>(&uv[j].x));
                float2 v1 = __half22float2(*reinterpret_cast<__half2*>(&uv[j].y));
                acc.x += v0.x * wv[j]; acc.y += v0.y * wv[j];
                acc.z += v1.x * wv[j]; acc.w += v1.y * wv[j];
            }
        }
    }

    float4 bb = reinterpret_cast<const float4*>(b)[lane];
    acc.x = fmaxf(acc.x + bb.x, 0.f);
    acc.y = fmaxf(acc.y + bb.y, 0.f);
    acc.z = fmaxf(acc.z + bb.z, 0.f);
    acc.w = fmaxf(acc.w + bb.w, 0.f);
    return acc;
}

// ---------------- gather1: writes g_a2 (fp16) ----------------
__global__ void k_gather(const float* __restrict__ b) {
    const int lane = threadIdx.x & 31;
    int node = blockIdx.x * (blockDim.x >> 5) + (threadIdx.x >> 5);
    if (node >= NN) return;
    float4 acc = gather_node(node, lane, b);
    reinterpret_cast<uint2*>(g_a2)[node * 32 + lane] =
        make_uint2(h2_pack(acc.x, acc.y), h2_pack(acc.z, acc.w));
}

// ---------------- gather2 + FC fused: writes logits directly ----------------
__global__ void k_gather_fc(const float* __restrict__ b,
                            const float* __restrict__ Wfc,
                            const float* __restrict__ bfc,
                            float* __restrict__ out) {
    __shared__ float WsT[NC * HID];  // [c][k]
    __shared__ float bs[NC];
    for (int i = threadIdx.x; i < NC * HID; i += blockDim.x) {
        int c = i >> 7;
        int k = i & 127;
        WsT[i] = Wfc[k * NC + c];
    }
    if (threadIdx.x < NC) bs[threadIdx.x] = bfc[threadIdx.x];
    __syncthreads();

    const int lane = threadIdx.x & 31;
    int node = blockIdx.x * (blockDim.x >> 5) + (threadIdx.x >> 5);
    if (node >= NN) return;
    float4 a = gather_node(node, lane, b);

#pragma unroll
    for (int c = 0; c < NC; c++) {
        const float4 w = reinterpret_cast<const float4*>(WsT + c * HID)[lane];
        float p = a.x * w.x + a.y * w.y + a.z * w.z + a.w * w.w;
        p += __shfl_xor_sync(0xffffffffu, p, 16);
        p += __shfl_xor_sync(0xffffffffu, p, 8);
        p += __shfl_xor_sync(0xffffffffu, p, 4);
        p += __shfl_xor_sync(0xffffffffu, p, 2);
        p += __shfl_xor_sync(0xffffffffu, p, 1);
        if (lane == 0) out[node * NC + c] = p + bs[c];
    }
}

// ---------------- launch ----------------
extern "C" void kernel_launch(void* const* d_in, const int* in_sizes, int n_in,
                              void* d_out, int out_size) {
    const float* x  = (const float*)d_in[0];
    const int* ei   = (const int*)d_in[1];   // int32 (JAX x64 disabled)
    const float* W1 = (const float*)d_in[2];
    const float* b1 = (const float*)d_in[3];
    const float* W2 = (const float*)d_in[4];
    const float* b2 = (const float*)d_in[5];
    const float* Wfc = (const float*)d_in[6];
    const float* bfc = (const float*)d_in[7];
    float* out = (float*)d_out;

    static cudaStream_t s2 = nullptr;
    static cudaEvent_t evFork = nullptr, evJoin = nullptr;
    if (!s2) {
        cudaStreamCreate(&s2);
        cudaEventCreateWithFlags(&evFork, cudaEventDisableTiming);
        cudaEventCreateWithFlags(&evJoin, cudaEventDisableTiming);
    }

    const int T = 256;
    const int nBlk = (NN + T - 1) / T;
    const int eBlk4 = (EE / 4 + T - 1) / T;
    const int gemmBlocks = (NN + BM - 1) / BM;   // 391
    const int warpBlocks = (NN + 7) / 8;

    // fork: GEMM1 (independent of graph structure) on side stream
    cudaEventRecord(evFork, 0);
    cudaStreamWaitEvent(s2, evFork, 0);
    k_gemm_fp16<<<gemmBlocks, 256, 0, s2>>>(x, W1);

    // CSR build chain on main stream (concurrent with GEMM1)
    k_init<<<nBlk, T>>>();
    k_deg_count<<<eBlk4, T>>>(ei);
    k_scan1<<<NB, SCAN_T>>>();
    k_scan3<<<nBlk, T>>>();
    k_bin<<<eBlk4, T>>>(ei);

    // join
    cudaEventRecord(evJoin, s2);
    cudaStreamWaitEvent(0, evJoin, 0);

    // conv1 aggregate -> GEMM2 (fp16 A path) -> fused conv2-aggregate+FC
    k_gather<<<warpBlocks, T>>>(b1);
    k_gemm_fp16<<<gemmBlocks, 256>>>(nullptr, W2);
    k_gather_fc<<<warpBlocks, T>>>(b2, Wfc, bfc, out);
}